// round 15
// baseline (speedup 1.0000x reference)
#include <cuda_runtime.h>
#include <cuda_fp16.h>
#include <math.h>
#include <stddef.h>
#include <stdint.h>

#define NHEADS 8
#define DIMH   64
#define NTOK   8192
#define BHN    16
#define ML     256
#define LGRP   32
#define DIM    512

// ---------------- scratch ----------------
__device__ float g_q [BHN*NTOK*DIMH];
__device__ float g_k [BHN*NTOK*DIMH];
__device__ float g_v [BHN*NTOK*DIMH];
__device__ __half g_vh[BHN*NTOK*DIMH];   // fp16 shadow of v for gemm_hh
__device__ float g_ql[BHN*ML*DIMH];
__device__ float g_kl[BHN*ML*DIMH];
__device__ __half g_attn1h[33554432];  // [bh][8192][256] fp16 softmax weights
__device__ __half g_attn3h[33554432];  // [bh][256][8192] fp16 exp(scores)
__device__ float g_rsp[BHN*ML*64*2];
__device__ float g_rs [BHN*ML];
__device__ float g_a2 [BHN*ML*ML];
__device__ float g_xz [BHN*ML*ML];
__device__ float g_xz2[BHN*ML*ML];
__device__ float g_w  [BHN*ML*ML];
__device__ float g_u  [BHN*ML*ML];
__device__ float g_z  [BHN*ML*ML];
__device__ float g_z2 [BHN*ML*ML];
__device__ float g_t3p[16*BHN*ML*DIMH];
__device__ float g_t3 [BHN*ML*DIMH];
__device__ float g_t2 [BHN*ML*DIMH];
__device__ float g_oh [BHN*NTOK*DIMH];
__device__ int   g_scal[2];

// ---------------- primitives ----------------
__device__ __forceinline__ void mma_tf32(float* d, const unsigned* a, const unsigned* b) {
    asm volatile("mma.sync.aligned.m16n8k8.row.col.f32.tf32.tf32.f32 "
        "{%0,%1,%2,%3}, {%4,%5,%6,%7}, {%8,%9}, {%0,%1,%2,%3};"
        : "+f"(d[0]), "+f"(d[1]), "+f"(d[2]), "+f"(d[3])
        : "r"(a[0]), "r"(a[1]), "r"(a[2]), "r"(a[3]), "r"(b[0]), "r"(b[1]));
}
__device__ __forceinline__ void mma_f16(float* d, const unsigned* a, const unsigned* b) {
    asm volatile("mma.sync.aligned.m16n8k16.row.col.f32.f16.f16.f32 "
        "{%0,%1,%2,%3}, {%4,%5,%6,%7}, {%8,%9}, {%0,%1,%2,%3};"
        : "+f"(d[0]), "+f"(d[1]), "+f"(d[2]), "+f"(d[3])
        : "r"(a[0]), "r"(a[1]), "r"(a[2]), "r"(a[3]), "r"(b[0]), "r"(b[1]));
}
__device__ __forceinline__ void cp16(uint32_t s, const void* g) {
    asm volatile("cp.async.cg.shared.global [%0], [%1], 16;\n" :: "r"(s), "l"(g));
}
__device__ __forceinline__ void cp_commit() {
    asm volatile("cp.async.commit_group;\n" ::: "memory");
}
__device__ __forceinline__ void cp_wait0() {
    asm volatile("cp.async.wait_group 0;\n" ::: "memory");
}
__device__ __forceinline__ void cp_wait1() {
    asm volatile("cp.async.wait_group 1;\n" ::: "memory");
}
__device__ __forceinline__ uint32_t s2u(const void* p) {
    return (uint32_t)__cvta_generic_to_shared(p);
}
__device__ __forceinline__ unsigned fu(float f) { return __float_as_uint(f); }
__device__ __forceinline__ unsigned h2tf(__half h) { return __float_as_uint(__half2float(h)); }

// ---------------- functors ----------------
struct AP {
    const float* p; int ld; size_t bs;
    __device__ __forceinline__ const void* src(int bz, int r, int k) const {
        return p + (size_t)bz*bs + (size_t)r*ld + k;
    }
};
struct BP {
    const float* p; int ld; size_t bs;
    __device__ __forceinline__ const void* src(int bz, int k, int n) const {
        return p + (size_t)bz*bs + (size_t)k*ld + n;
    }
};
struct BTmat {
    const float* p; int ld; size_t bs;
    __device__ __forceinline__ const void* srcT(int bz, int c, int k) const {
        return p + (size_t)bz*bs + (size_t)c*ld + k;
    }
};
// half functors
struct AHSplit {            // a3h [bh][256][8192], bz = bh*16 + split
    const __half* p;
    __device__ __forceinline__ const void* src(int bz, int r, int k) const {
        int bh = bz >> 4, sp = bz & 15;
        return p + ((size_t)bh*ML + r)*NTOK + sp*512 + k;
    }
};
struct AH1 {                // a1h [bh][8192][256]
    const __half* p;
    __device__ __forceinline__ const void* src(int bz, int r, int k) const {
        return p + ((size_t)bz*NTOK + r)*256 + k;
    }
};
struct BHSplit {            // vh [bh][8192][64], bz = bh*16 + split
    const __half* p;
    __device__ __forceinline__ const void* src(int bz, int k, int n) const {
        int bh = bz >> 4, sp = bz & 15;
        return p + ((size_t)bh*NTOK + sp*512 + k)*64 + n;
    }
};
struct AGather {
    const float* p;
    __device__ __forceinline__ const void* src(int bz, int r, int k) const {
        int b = r >> 13, t = r & (NTOK-1), head = k >> 6, dd = k & 63;
        return p + (((size_t)(b*8+head))*NTOK + t)*64 + dd;
    }
};
// pinv pair-GEMM
struct APair {
    const float* z; const float* xz;
    __device__ __forceinline__ const void* src(int bz, int r, int k) const {
        const float* base = (bz < 16) ? (z  + (size_t)bz*65536)
                                      : (xz + (size_t)(bz-16)*65536);
        return base + (size_t)r*256 + k;
    }
};
struct BPu {
    const float* u;
    __device__ __forceinline__ const void* src(int bz, int k, int n) const {
        return u + (size_t)(bz & 15)*65536 + (size_t)k*256 + n;
    }
};
struct EPair {
    float* z; float* xzn;
    __device__ __forceinline__ void store(int bz, int r, int c, float v) const {
        float* base = (bz < 16) ? (z   + (size_t)bz*65536)
                                : (xzn + (size_t)(bz-16)*65536);
        base[(size_t)r*256 + c] = 0.25f * v;
    }
};
struct ES {
    float* p; int ld; size_t bs; float scale;
    __device__ __forceinline__ void store(int bz, int r, int c, float v) const {
        p[(size_t)bz*bs + (size_t)r*ld + c] = v*scale;
    }
};
struct EDiag {
    float* p; float alpha;
    __device__ __forceinline__ void store(int bz, int r, int c, float v) const {
        p[(size_t)bz*65536 + (size_t)r*256 + c] = ((r==c)?alpha:0.f) - v;
    }
};
struct EW {
    const float* xz; float* w;
    __device__ __forceinline__ void store(int bz, int r, int c, float v) const {
        size_t o = (size_t)bz*65536 + (size_t)r*256 + c;
        w[o] = ((r==c)?15.f:0.f) - 7.f*xz[o] + v;
    }
};
struct EQKV {
    float* q; float* k; float* v; __half* vh;
    __device__ __forceinline__ void store(int bz, int r, int c, float acc) const {
        int b = r >> 13, t = r & (NTOK-1);
        int which = c >> 9, head = (c >> 6) & 7, dd = c & 63;
        float* dst = (which==0) ? q : ((which==1) ? k : v);
        if (which == 0) acc *= 0.125f;
        size_t o = (((size_t)(b*8+head))*NTOK + t)*64 + dd;
        dst[o] = acc;
        if (which == 2) vh[o] = __float2half_rn(acc);
    }
};
struct EPart {
    float* p;
    __device__ __forceinline__ void store(int bz, int r, int c, float v) const {
        int bh = bz >> 4, sp = bz & 15;
        p[(((size_t)sp*BHN + bh)*ML + r)*64 + c] = v;
    }
};
struct EFin {
    const float* x; const float* bo; float* out;
    __device__ __forceinline__ void store(int bz, int r, int c, float v) const {
        size_t i = (size_t)r*DIM + c;
        out[i] = x[i] + bo[c] + v;
    }
};

// ---------------- general tf32 tensor-core GEMM, cp.async double-buffered ---
template<int BM, int BN, int WM, int WN, bool BT, class FA, class FB, class FE>
__global__ __launch_bounds__((BM/WM)*(BN/WN)*32)
void gemm_tc(FA fa, FB fb, FE fe, int K) {
    constexpr int NTHR = (BM/WM)*(BN/WN)*32;
    constexpr int LDA = 20;
    constexpr int LDB = BN + 4;
    constexpr int MT = WM/16, NT = WN/8;
    constexpr int BSZ = BT ? 2*BN*20 : 2*16*LDB;
    __shared__ float As[2*BM*LDA];
    __shared__ float Bs[BSZ];
    const int tid = threadIdx.x;
    const int wid = tid >> 5, lane = tid & 31;
    const int qd = lane >> 2, tq = lane & 3;
    const int wm = (wid / (BN/WN)) * WM, wn = (wid % (BN/WN)) * WN;
    const int m0 = blockIdx.y * BM, n0 = blockIdx.x * BN, bz = blockIdx.z;
    const uint32_t sA = s2u(As), sB = s2u(Bs);

    float acc[MT][NT][4] = {};

    auto load_tile = [&](int k0, int buf) {
        const uint32_t ab = sA + buf*BM*LDA*4;
#pragma unroll
        for (int i = tid; i < BM*4; i += NTHR) {
            int r = i >> 2, kq = (i & 3) << 2;
            cp16(ab + (r*LDA + kq)*4, fa.src(bz, m0 + r, k0 + kq));
        }
        if constexpr (BT) {
            const uint32_t bb = sB + buf*BN*20*4;
#pragma unroll
            for (int i = tid; i < BN*4; i += NTHR) {
                int n = i >> 2, kq = (i & 3) << 2;
                cp16(bb + (n*20 + kq)*4, fb.srcT(bz, n0 + n, k0 + kq));
            }
        } else {
            const uint32_t bb = sB + buf*16*LDB*4;
#pragma unroll
            for (int i = tid; i < BN*4; i += NTHR) {
                int kk = i / (BN/4), nq = (i % (BN/4)) * 4;
                cp16(bb + (kk*LDB + nq)*4, fb.src(bz, k0 + kk, n0 + nq));
            }
        }
        cp_commit();
    };

    load_tile(0, 0);
    const int T = K >> 4;
    for (int t = 0; t < T; t++) {
        if (t + 1 < T) { load_tile((t+1) << 4, (t+1) & 1); cp_wait1(); }
        else           { cp_wait0(); }
        __syncthreads();
        const float* Ab = As + (t & 1)*BM*LDA;
        const float* Bb = BT ? (Bs + (t & 1)*BN*20) : (Bs + (t & 1)*16*LDB);
#pragma unroll
        for (int ks = 0; ks < 16; ks += 8) {
            unsigned af[MT][4];
#pragma unroll
            for (int mt = 0; mt < MT; mt++) {
                int mm = wm + mt*16 + qd;
                af[mt][0] = fu(Ab[ mm     *LDA + ks + tq    ]);
                af[mt][1] = fu(Ab[(mm + 8)*LDA + ks + tq    ]);
                af[mt][2] = fu(Ab[ mm     *LDA + ks + tq + 4]);
                af[mt][3] = fu(Ab[(mm + 8)*LDA + ks + tq + 4]);
            }
#pragma unroll
            for (int nt = 0; nt < NT; nt++) {
                int nn = wn + nt*8 + qd;
                unsigned bf[2];
                if constexpr (BT) {
                    bf[0] = fu(Bb[nn*20 + ks + tq    ]);
                    bf[1] = fu(Bb[nn*20 + ks + tq + 4]);
                } else {
                    bf[0] = fu(Bb[(ks + tq    )*LDB + nn]);
                    bf[1] = fu(Bb[(ks + tq + 4)*LDB + nn]);
                }
#pragma unroll
                for (int mt = 0; mt < MT; mt++)
                    mma_tf32(acc[mt][nt], af[mt], bf);
            }
        }
        __syncthreads();
    }
#pragma unroll
    for (int mt = 0; mt < MT; mt++)
#pragma unroll
        for (int nt = 0; nt < NT; nt++) {
            int r = m0 + wm + mt*16 + qd;
            int c = n0 + wn + nt*8 + tq*2;
            fe.store(bz, r,   c,   acc[mt][nt][0]);
            fe.store(bz, r,   c+1, acc[mt][nt][1]);
            fe.store(bz, r+8, c,   acc[mt][nt][2]);
            fe.store(bz, r+8, c+1, acc[mt][nt][3]);
        }
}

// ------- fp16 x fp16 HMMA GEMM (m16n8k16), both operands k-contiguous -------
template<int BM, int BN, int WM, int WN, class FA, class FB, class FE>
__global__ __launch_bounds__((BM/WM)*(BN/WN)*32)
void gemm_hh(FA fa, FB fb, FE fe, int K) {
    constexpr int NTHR = (BM/WM)*(BN/WN)*32;
    constexpr int LDAH = 24;           // halves: 16 data + 8 pad
    constexpr int LDBH = BN + 8;       // halves per B row
    constexpr int MT = WM/16, NT = WN/8;
    __shared__ __half As[2*BM*LDAH];
    __shared__ __half Bs[2*16*LDBH];
    const int tid = threadIdx.x;
    const int wid = tid >> 5, lane = tid & 31;
    const int qd = lane >> 2, tq = lane & 3;
    const int wm = (wid / (BN/WN)) * WM, wn = (wid % (BN/WN)) * WN;
    const int m0 = blockIdx.y * BM, n0 = blockIdx.x * BN, bz = blockIdx.z;
    const uint32_t sA = s2u(As), sB = s2u(Bs);

    float acc[MT][NT][4] = {};

    auto load_tile = [&](int k0, int buf) {
        const uint32_t ab = sA + buf*BM*LDAH*2;
#pragma unroll
        for (int i = tid; i < BM*2; i += NTHR) {
            int r = i >> 1, kh = (i & 1) << 3;    // 8 halves per cp16
            cp16(ab + (r*LDAH + kh)*2, fa.src(bz, m0 + r, k0 + kh));
        }
        const uint32_t bb = sB + buf*16*LDBH*2;
#pragma unroll
        for (int i = tid; i < BN*2; i += NTHR) {
            int kk = i / (BN/8), nq = (i % (BN/8)) * 8;
            cp16(bb + (kk*LDBH + nq)*2, fb.src(bz, k0 + kk, n0 + nq));
        }
        cp_commit();
    };

    load_tile(0, 0);
    const int T = K >> 4;
    for (int t = 0; t < T; t++) {
        if (t + 1 < T) { load_tile((t+1) << 4, (t+1) & 1); cp_wait1(); }
        else           { cp_wait0(); }
        __syncthreads();
        const __half* Ab = As + (t & 1)*BM*LDAH;
        const __half* Bb = Bs + (t & 1)*16*LDBH;
        unsigned af[MT][4];
#pragma unroll
        for (int mt = 0; mt < MT; mt++) {
            int mm = wm + mt*16 + qd;
            af[mt][0] = *(const unsigned*)(Ab +  mm     *LDAH + 2*tq    );
            af[mt][1] = *(const unsigned*)(Ab + (mm + 8)*LDAH + 2*tq    );
            af[mt][2] = *(const unsigned*)(Ab +  mm     *LDAH + 2*tq + 8);
            af[mt][3] = *(const unsigned*)(Ab + (mm + 8)*LDAH + 2*tq + 8);
        }
#pragma unroll
        for (int nt = 0; nt < NT; nt++) {
            int nn = wn + nt*8 + qd;
            unsigned bf[2];
            unsigned b00 = __half_as_ushort(Bb[(2*tq    )*LDBH + nn]);
            unsigned b01 = __half_as_ushort(Bb[(2*tq + 1)*LDBH + nn]);
            unsigned b10 = __half_as_ushort(Bb[(2*tq + 8)*LDBH + nn]);
            unsigned b11 = __half_as_ushort(Bb[(2*tq + 9)*LDBH + nn]);
            bf[0] = b00 | (b01 << 16);
            bf[1] = b10 | (b11 << 16);
#pragma unroll
            for (int mt = 0; mt < MT; mt++)
                mma_f16(acc[mt][nt], af[mt], bf);
        }
        __syncthreads();
    }
#pragma unroll
    for (int mt = 0; mt < MT; mt++)
#pragma unroll
        for (int nt = 0; nt < NT; nt++) {
            int r = m0 + wm + mt*16 + qd;
            int c = n0 + wn + nt*8 + tq*2;
            fe.store(bz, r,   c,   acc[mt][nt][0]);
            fe.store(bz, r,   c+1, acc[mt][nt][1]);
            fe.store(bz, r+8, c,   acc[mt][nt][2]);
            fe.store(bz, r+8, c+1, acc[mt][nt][3]);
        }
}

// ------- variant: A operand fp16, B fp32 (tf32 mma) -------------------------
template<int BM, int BN, int WM, int WN, class FA, class FB, class FE>
__global__ __launch_bounds__((BM/WM)*(BN/WN)*32)
void gemm_tc_ha(FA fa, FB fb, FE fe, int K) {
    constexpr int NTHR = (BM/WM)*(BN/WN)*32;
    constexpr int LDAH = 24;
    constexpr int LDB = BN + 4;
    constexpr int MT = WM/16, NT = WN/8;
    __shared__ __half As[2*BM*LDAH];
    __shared__ float  Bs[2*16*LDB];
    const int tid = threadIdx.x;
    const int wid = tid >> 5, lane = tid & 31;
    const int qd = lane >> 2, tq = lane & 3;
    const int wm = (wid / (BN/WN)) * WM, wn = (wid % (BN/WN)) * WN;
    const int m0 = blockIdx.y * BM, n0 = blockIdx.x * BN, bz = blockIdx.z;
    const uint32_t sA = s2u(As), sB = s2u(Bs);

    float acc[MT][NT][4] = {};

    auto load_tile = [&](int k0, int buf) {
        const uint32_t ab = sA + buf*BM*LDAH*2;
#pragma unroll
        for (int i = tid; i < BM*2; i += NTHR) {
            int r = i >> 1, kh = (i & 1) << 3;
            cp16(ab + (r*LDAH + kh)*2, fa.src(bz, m0 + r, k0 + kh));
        }
        const uint32_t bb = sB + buf*16*LDB*4;
#pragma unroll
        for (int i = tid; i < BN*4; i += NTHR) {
            int kk = i / (BN/4), nq = (i % (BN/4)) * 4;
            cp16(bb + (kk*LDB + nq)*4, fb.src(bz, k0 + kk, n0 + nq));
        }
        cp_commit();
    };

    load_tile(0, 0);
    const int T = K >> 4;
    for (int t = 0; t < T; t++) {
        if (t + 1 < T) { load_tile((t+1) << 4, (t+1) & 1); cp_wait1(); }
        else           { cp_wait0(); }
        __syncthreads();
        const __half* Ab = As + (t & 1)*BM*LDAH;
        const float*  Bb = Bs + (t & 1)*16*LDB;
#pragma unroll
        for (int ks = 0; ks < 16; ks += 8) {
            unsigned af[MT][4];
#pragma unroll
            for (int mt = 0; mt < MT; mt++) {
                int mm = wm + mt*16 + qd;
                af[mt][0] = h2tf(Ab[ mm     *LDAH + ks + tq    ]);
                af[mt][1] = h2tf(Ab[(mm + 8)*LDAH + ks + tq    ]);
                af[mt][2] = h2tf(Ab[ mm     *LDAH + ks + tq + 4]);
                af[mt][3] = h2tf(Ab[(mm + 8)*LDAH + ks + tq + 4]);
            }
#pragma unroll
            for (int nt = 0; nt < NT; nt++) {
                int nn = wn + nt*8 + qd;
                unsigned bf[2];
                bf[0] = fu(Bb[(ks + tq    )*LDB + nn]);
                bf[1] = fu(Bb[(ks + tq + 4)*LDB + nn]);
#pragma unroll
                for (int mt = 0; mt < MT; mt++)
                    mma_tf32(acc[mt][nt], af[mt], bf);
            }
        }
        __syncthreads();
    }
#pragma unroll
    for (int mt = 0; mt < MT; mt++)
#pragma unroll
        for (int nt = 0; nt < NT; nt++) {
            int r = m0 + wm + mt*16 + qd;
            int c = n0 + wn + nt*8 + tq*2;
            fe.store(bz, r,   c,   acc[mt][nt][0]);
            fe.store(bz, r,   c+1, acc[mt][nt][1]);
            fe.store(bz, r+8, c,   acc[mt][nt][2]);
            fe.store(bz, r+8, c+1, acc[mt][nt][3]);
        }
}

// ---------------- fused GEMM + row softmax: O = softmax(A @ B^T) -----------
template<class OutT>
__global__ __launch_bounds__(256)
void gemm_rowsmax(const float* __restrict__ A, size_t a_bs,
                  const float* __restrict__ B, size_t b_bs,
                  OutT* __restrict__ O, size_t o_bs) {
    extern __shared__ float sm[];
    float* As = sm;                 // [2][128][20]
    float* Bs = sm + 2*128*20;      // [256][68]
    const int tid = threadIdx.x, wid = tid >> 5, lane = tid & 31;
    const int qd = lane >> 2, tq = lane & 3;
    const int m0 = blockIdx.y * 128, bz = blockIdx.z;
    const float* Ag = A + (size_t)bz * a_bs;
    const float* Bg = B + (size_t)bz * b_bs;
    const uint32_t sA = s2u(As), sB = s2u(Bs);

#pragma unroll
    for (int i = tid; i < 256*4; i += 256) {
        int n = i >> 2, kq = (i & 3) << 2;
        cp16(sB + (n*68 + kq)*4, Bg + (size_t)n*64 + kq);
    }
#pragma unroll
    for (int i = tid; i < 128*4; i += 256) {
        int r = i >> 2, kq = (i & 3) << 2;
        cp16(sA + (r*20 + kq)*4, Ag + (size_t)(m0 + r)*64 + kq);
    }
    cp_commit();

    float acc[32][4] = {};
    for (int t = 0; t < 4; t++) {
        if (t < 3) {
            const uint32_t ab = sA + ((t+1) & 1)*128*20*4;
            const int k0 = (t+1) << 4;
#pragma unroll
            for (int i = tid; i < 128*4; i += 256) {
                int r = i >> 2, kq = (i & 3) << 2;
                cp16(ab + (r*20 + kq)*4, Ag + (size_t)(m0 + r)*64 + k0 + kq);
            }
            cp_commit();
            cp_wait1();
        } else cp_wait0();
        __syncthreads();
        const float* Ab = As + (t & 1)*128*20;
        const int kb = t << 4;
#pragma unroll
        for (int ks = 0; ks < 16; ks += 8) {
            unsigned af[4];
            int mm = wid*16 + qd;
            af[0] = fu(Ab[ mm     *20 + ks + tq    ]);
            af[1] = fu(Ab[(mm + 8)*20 + ks + tq    ]);
            af[2] = fu(Ab[ mm     *20 + ks + tq + 4]);
            af[3] = fu(Ab[(mm + 8)*20 + ks + tq + 4]);
#pragma unroll
            for (int nt = 0; nt < 32; nt++) {
                int nn = nt*8 + qd;
                unsigned bf[2];
                bf[0] = fu(Bs[nn*68 + kb + ks + tq    ]);
                bf[1] = fu(Bs[nn*68 + kb + ks + tq + 4]);
                mma_tf32(acc[nt], af, bf);
            }
        }
        __syncthreads();
    }
    float mx0 = -1e30f, mx1 = -1e30f;
#pragma unroll
    for (int nt = 0; nt < 32; nt++) {
        mx0 = fmaxf(mx0, fmaxf(acc[nt][0], acc[nt][1]));
        mx1 = fmaxf(mx1, fmaxf(acc[nt][2], acc[nt][3]));
    }
#pragma unroll
    for (int s = 1; s < 4; s <<= 1) {
        mx0 = fmaxf(mx0, __shfl_xor_sync(0xffffffffu, mx0, s));
        mx1 = fmaxf(mx1, __shfl_xor_sync(0xffffffffu, mx1, s));
    }
    float s0 = 0.f, s1 = 0.f;
#pragma unroll
    for (int nt = 0; nt < 32; nt++) {
        acc[nt][0] = __expf(acc[nt][0] - mx0);
        acc[nt][1] = __expf(acc[nt][1] - mx0);
        acc[nt][2] = __expf(acc[nt][2] - mx1);
        acc[nt][3] = __expf(acc[nt][3] - mx1);
        s0 += acc[nt][0] + acc[nt][1];
        s1 += acc[nt][2] + acc[nt][3];
    }
#pragma unroll
    for (int s = 1; s < 4; s <<= 1) {
        s0 += __shfl_xor_sync(0xffffffffu, s0, s);
        s1 += __shfl_xor_sync(0xffffffffu, s1, s);
    }
    const float i0 = 1.f / s0, i1 = 1.f / s1;
    const int r0 = m0 + wid*16 + qd;
    OutT* O0 = O + (size_t)bz*o_bs + (size_t)r0*256;
#pragma unroll
    for (int nt = 0; nt < 32; nt++) {
        int c = nt*8 + tq*2;
        if constexpr (sizeof(OutT) == 4) {
            *(float2*)((float*)O0 + c)         = make_float2(acc[nt][0]*i0, acc[nt][1]*i0);
            *(float2*)((float*)O0 + 8*256 + c) = make_float2(acc[nt][2]*i1, acc[nt][3]*i1);
        } else {
            *(__half2*)((__half*)O0 + c)         = __floats2half2_rn(acc[nt][0]*i0, acc[nt][1]*i0);
            *(__half2*)((__half*)O0 + 8*256 + c) = __floats2half2_rn(acc[nt][2]*i1, acc[nt][3]*i1);
        }
    }
}

// ------- sim3 with fused exp (fp16 store) + fp32 row-sum partials -----------
__global__ __launch_bounds__(128)
void sim3_exp_k(const float* __restrict__ QL, const float* __restrict__ Kg,
                __half* __restrict__ A3, float* __restrict__ RSP) {
    constexpr int LDA = 20;
    __shared__ float As[2*128*LDA];
    __shared__ float Bs[2*128*LDA];
    const int tid = threadIdx.x;
    const int wid = tid >> 5, lane = tid & 31;
    const int qd = lane >> 2, tq = lane & 3;
    const int wm = (wid >> 1) * 64, wn = (wid & 1) * 64;
    const int n0 = blockIdx.x * 128, m0 = blockIdx.y * 128;
    const int bz = blockIdx.z;
    const float* Ag = QL + (size_t)bz * ML * 64;
    const float* Bg = Kg + (size_t)bz * NTOK * 64;
    const uint32_t sA = s2u(As), sB = s2u(Bs);

    float acc[4][8][4] = {};
    auto load_tile = [&](int k0, int buf) {
        const uint32_t ab = sA + buf*128*LDA*4;
#pragma unroll
        for (int i = tid; i < 128*4; i += 128) {
            int r = i >> 2, kq = (i & 3) << 2;
            cp16(ab + (r*LDA + kq)*4, Ag + (size_t)(m0 + r)*64 + k0 + kq);
        }
        const uint32_t bb = s2u(Bs) + buf*128*LDA*4;
#pragma unroll
        for (int i = tid; i < 128*4; i += 128) {
            int n = i >> 2, kq = (i & 3) << 2;
            cp16(bb + (n*LDA + kq)*4, Bg + (size_t)(n0 + n)*64 + k0 + kq);
        }
        cp_commit();
    };

    load_tile(0, 0);
    for (int t = 0; t < 4; t++) {
        if (t + 1 < 4) { load_tile((t+1) << 4, (t+1) & 1); cp_wait1(); }
        else           { cp_wait0(); }
        __syncthreads();
        const float* Ab = As + (t & 1)*128*LDA;
        const float* Bb = Bs + (t & 1)*128*LDA;
#pragma unroll
        for (int ks = 0; ks < 16; ks += 8) {
            unsigned af[4][4];
#pragma unroll
            for (int mt = 0; mt < 4; mt++) {
                int mm = wm + mt*16 + qd;
                af[mt][0] = fu(Ab[ mm     *LDA + ks + tq    ]);
                af[mt][1] = fu(Ab[(mm + 8)*LDA + ks + tq    ]);
                af[mt][2] = fu(Ab[ mm     *LDA + ks + tq + 4]);
                af[mt][3] = fu(Ab[(mm + 8)*LDA + ks + tq + 4]);
            }
#pragma unroll
            for (int nt = 0; nt < 8; nt++) {
                int nn = wn + nt*8 + qd;
                unsigned bf[2];
                bf[0] = fu(Bb[nn*LDA + ks + tq    ]);
                bf[1] = fu(Bb[nn*LDA + ks + tq + 4]);
#pragma unroll
                for (int mt = 0; mt < 4; mt++)
                    mma_tf32(acc[mt][nt], af[mt], bf);
            }
        }
        __syncthreads();
    }

    __half* a3b = A3 + (size_t)bz * ML * NTOK;
    const int wh = wid & 1;
#pragma unroll
    for (int mt = 0; mt < 4; mt++) {
        const int r = wm + mt*16 + qd;
        float slo = 0.f, shi = 0.f;
#pragma unroll
        for (int nt = 0; nt < 8; nt++) {
            int c = n0 + wn + nt*8 + tq*2;
            float e0 = __expf(acc[mt][nt][0]);
            float e1 = __expf(acc[mt][nt][1]);
            float e2 = __expf(acc[mt][nt][2]);
            float e3 = __expf(acc[mt][nt][3]);
            *(__half2*)(a3b + (size_t)(m0 + r    )*NTOK + c) = __floats2half2_rn(e0, e1);
            *(__half2*)(a3b + (size_t)(m0 + r + 8)*NTOK + c) = __floats2half2_rn(e2, e3);
            slo += e0 + e1;
            shi += e2 + e3;
        }
#pragma unroll
        for (int s = 1; s < 4; s <<= 1) {
            slo += __shfl_xor_sync(0xffffffffu, slo, s);
            shi += __shfl_xor_sync(0xffffffffu, shi, s);
        }
        if (tq == 0) {
            RSP[(((size_t)bz*ML + (m0 + r    ))*64 + blockIdx.x)*2 + wh] = slo;
            RSP[(((size_t)bz*ML + (m0 + r + 8))*64 + blockIdx.x)*2 + wh] = shi;
        }
    }
}

__global__ __launch_bounds__(256)
void rowsum_k(const float* __restrict__ rsp, float* __restrict__ rs) {
    int row = blockIdx.x * 8 + (threadIdx.x >> 5);
    int lane = threadIdx.x & 31;
    const float* p = rsp + (size_t)row * 128;
    float s = p[lane] + p[lane + 32] + p[lane + 64] + p[lane + 96];
#pragma unroll
    for (int sh = 16; sh > 0; sh >>= 1) s += __shfl_xor_sync(0xffffffffu, s, sh);
    if (lane == 0) rs[row] = s;
}

// ---------------- small kernels ----------------
__global__ void init_scal_k(int* scal) { if (threadIdx.x < 2) scal[threadIdx.x] = 0; }

__global__ __launch_bounds__(256) void landmarks_k(
        const float* __restrict__ q, const float* __restrict__ k,
        float* __restrict__ ql, float* __restrict__ kl) {
    int idx = blockIdx.x * 256 + threadIdx.x;
    int dd = idx & 63, j = (idx >> 6) & 255, bh = idx >> 14;
    const float* qp = q + ((size_t)bh*NTOK + (size_t)j*LGRP)*64 + dd;
    const float* kp = k + ((size_t)bh*NTOK + (size_t)j*LGRP)*64 + dd;
    float sq = 0.f, sk = 0.f;
#pragma unroll
    for (int t = 0; t < LGRP; t++) { sq += qp[(size_t)t*64]; sk += kp[(size_t)t*64]; }
    ql[idx] = sq * (1.f/LGRP);
    kl[idx] = sk * (1.f/LGRP);
}

__global__ __launch_bounds__(256) void scal_reduce_k(const float* __restrict__ a2, int* scal) {
    int idx = blockIdx.x, bh = blockIdx.y, mode = blockIdx.z, tid = threadIdx.x;
    const float* base = a2 + (size_t)bh * 65536;
    float v = (mode == 0) ? base[(size_t)idx*256 + tid] : base[(size_t)tid*256 + idx];
    __shared__ float red[256];
    red[tid] = v; __syncthreads();
    for (int s = 128; s > 0; s >>= 1) { if (tid < s) red[tid] += red[tid+s]; __syncthreads(); }
    if (tid == 0) atomicMax(&scal[mode], __float_as_int(red[0]));
}

__global__ __launch_bounds__(256) void zinit_k(const float* __restrict__ a2,
                                               const int* __restrict__ scal,
                                               float* __restrict__ z) {
    size_t idx = (size_t)blockIdx.x * 256 + threadIdx.x;
    float col = __int_as_float(scal[0]), row = __int_as_float(scal[1]);
    float rcp = 1.f / (col * row);
    int j = (int)(idx & 255), i = (int)((idx >> 8) & 255);
    size_t bh = idx >> 16;
    z[idx] = a2[(bh << 16) + (size_t)j*256 + i] * rcp;
}

__global__ __launch_bounds__(256) void t3_reduce_k(const float* __restrict__ part,
                                                   const float* __restrict__ rs,
                                                   float* __restrict__ t3) {
    int idx = blockIdx.x * 256 + threadIdx.x;
    float s = 0.f;
#pragma unroll
    for (int sp = 0; sp < 16; sp++) s += part[(size_t)sp*262144 + idx];
    t3[idx] = s / rs[idx >> 6];
}

// -------- tiled depthwise conv ----------
__global__ __launch_bounds__(256) void conv_add_k(const float* __restrict__ v,
                                                  const float* __restrict__ wc,
                                                  float* __restrict__ oh) {
    __shared__ float vt[160*64];
    const int chunk = blockIdx.x, bh = blockIdx.y;
    const int h = bh & 7;
    const int tid = threadIdx.x;
    const float* vb = v + (size_t)bh * NTOK * 64;
    const int base = chunk * 128 - 16;

    for (int idx = tid; idx < 160*64; idx += 256) {
        int row = idx >> 6, dd = idx & 63;
        int src = base + row;
        vt[idx] = (src >= 0 && src < NTOK) ? vb[(size_t)src*64 + dd] : 0.f;
    }
    float wreg[33];
#pragma unroll
    for (int t = 0; t < 33; t++) wreg[t] = wc[h*33 + t];
    __syncthreads();

    const int dd = tid & 63, quarter = tid >> 6;
    float vr[64];
#pragma unroll
    for (int x = 0; x < 64; x++) vr[x] = vt[(quarter*32 + x)*64 + dd];

    float* ohb = oh + ((size_t)bh*NTOK + (size_t)chunk*128 + quarter*32)*64 + dd;
#pragma unroll
    for (int j = 0; j < 32; j++) {
        float s = 0.f;
#pragma unroll
        for (int t = 0; t < 33; t++) s += wreg[t] * vr[j + t];
        ohb[(size_t)j*64] += s;
    }
}

// ---------------- orchestration ----------------
extern "C" void kernel_launch(void* const* d_in, const int* in_sizes, int n_in,
                              void* d_out, int out_size) {
    (void)in_sizes; (void)n_in; (void)out_size;
    const float* x      = (const float*)d_in[0];
    const float* w_qkv  = (const float*)d_in[1];
    const float* w_out  = (const float*)d_in[2];
    const float* b_out  = (const float*)d_in[3];
    const float* w_conv = (const float*)d_in[4];
    float* out = (float*)d_out;

    float *q,*k,*v,*ql,*kl,*rsp,*rs,*a2,*xz,*xz2,*w,*u,*z,*z2,*t3p,*t3,*t2,*oh;
    __half *a1h, *a3h, *vh;
    int* scal;
    cudaGetSymbolAddress((void**)&q,  g_q);
    cudaGetSymbolAddress((void**)&k,  g_k);
    cudaGetSymbolAddress((void**)&v,  g_v);
    cudaGetSymbolAddress((void**)&vh, g_vh);
    cudaGetSymbolAddress((void**)&ql, g_ql);
    cudaGetSymbolAddress((void**)&kl, g_kl);
    cudaGetSymbolAddress((void**)&a1h,g_attn1h);
    cudaGetSymbolAddress((void**)&a3h,g_attn3h);
    cudaGetSymbolAddress((void**)&rsp,g_rsp);
    cudaGetSymbolAddress((void**)&rs, g_rs);
    cudaGetSymbolAddress((void**)&a2, g_a2);
    cudaGetSymbolAddress((void**)&xz, g_xz);
    cudaGetSymbolAddress((void**)&xz2,g_xz2);
    cudaGetSymbolAddress((void**)&w,  g_w);
    cudaGetSymbolAddress((void**)&u,  g_u);
    cudaGetSymbolAddress((void**)&z,  g_z);
    cudaGetSymbolAddress((void**)&z2, g_z2);
    cudaGetSymbolAddress((void**)&t3p,g_t3p);
    cudaGetSymbolAddress((void**)&t3, g_t3);
    cudaGetSymbolAddress((void**)&t2, g_t2);
    cudaGetSymbolAddress((void**)&oh, g_oh);
    cudaGetSymbolAddress((void**)&scal, g_scal);

    static bool attr_done = false;
    if (!attr_done) {
        cudaFuncSetAttribute(gemm_rowsmax<float>,
            cudaFuncAttributeMaxDynamicSharedMemorySize, 90112);
        cudaFuncSetAttribute(gemm_rowsmax<__half>,
            cudaFuncAttributeMaxDynamicSharedMemorySize, 90112);
        attr_done = true;
    }

    init_scal_k<<<1, 32>>>(scal);

    // 1. QKV projection (BK16 proven config; also emits fp16 v shadow)
    gemm_tc<128,128,64,64,false><<<dim3(12, 128, 1), 128>>>(
        AP{x, DIM, 0}, BP{w_qkv, 1536, 0}, EQKV{q, k, v, vh}, DIM);

    // 2. landmark means
    landmarks_k<<<1024, 256>>>(q, k, ql, kl);

    // 3. attn2 = softmax(ql @ kl^T), fused (fp32 — feeds pinv)
    gemm_rowsmax<float><<<dim3(1, 2, BHN), 256, 90112>>>(
        ql, (size_t)ML*64, kl, (size_t)ML*64, a2, (size_t)ML*256);

    // 4. pinv init
    scal_reduce_k<<<dim3(256, BHN, 2), 256>>>(a2, scal);
    zinit_k<<<4096, 256>>>(a2, scal, z);

    // 5. Newton–Schulz x6, 3 GEMMs/iter
    float* xzc = xz;
    float* xzn = xz2;
    gemm_tc<64,64,32,32,false><<<dim3(4,4,BHN), 128>>>(
        AP{a2,256,65536}, BP{z,256,65536}, ES{xzc,256,65536,1.f}, 256);
    for (int it = 0; it < 6; it++) {
        float* zin  = (it & 1) ? z2 : z;
        float* zout = (it & 1) ? z  : z2;
        gemm_tc<64,64,32,32,false><<<dim3(4,4,BHN), 128>>>(
            AP{xzc,256,65536}, BP{xzc,256,65536}, EW{xzc, w}, 256);
        gemm_tc<64,64,32,32,false><<<dim3(4,4,BHN), 128>>>(
            AP{xzc,256,65536}, BP{w,256,65536}, EDiag{u,13.f}, 256);
        if (it < 5) {
            gemm_tc<64,64,32,32,false><<<dim3(4,4,2*BHN), 128>>>(
                APair{zin, xzc}, BPu{u}, EPair{zout, xzn}, 256);
            float* tmp = xzc; xzc = xzn; xzn = tmp;
        } else {
            gemm_tc<64,64,32,32,false><<<dim3(4,4,BHN), 128>>>(
                AP{zin,256,65536}, BP{u,256,65536}, ES{zout,256,65536,0.25f}, 256);
        }
    }
    // final z in g_z

    // 6. attn1 = softmax(q @ kl^T) -> fp16
    gemm_rowsmax<__half><<<dim3(1, 64, BHN), 256, 90112>>>(
        q, (size_t)NTOK*64, kl, (size_t)ML*64, a1h, (size_t)NTOK*256);

    // 7. a3 = exp(ql @ k^T) -> fp16, fp32 row-sum partials
    sim3_exp_k<<<dim3(64, 2, BHN), 128>>>(ql, k, a3h, rsp);
    rowsum_k<<<512, 256>>>(rsp, rs);

    // 8. t3 = (exp-scores @ v) / rowsum  (full fp16 HMMA split-K x16)
    gemm_hh<128,64,64,32><<<dim3(1, 2, BHN*16), 128>>>(
        AHSplit{a3h}, BHSplit{vh}, EPart{t3p}, 512);
    t3_reduce_k<<<1024, 256>>>(t3p, rs, t3);

    // 9. t2 = z @ t3
    gemm_tc<128,64,64,32,false><<<dim3(1, 2, BHN), 128>>>(
        AP{z, 256, 65536}, BP{t3, 64, (size_t)ML*64},
        ES{t2, 64, (size_t)ML*64, 1.f}, 256);

    // 10. oh = attn1 @ t2  (half-A, fp32 B)
    gemm_tc_ha<128,64,64,32><<<dim3(1, 64, BHN), 128>>>(
        AH1{a1h}, BP{t2, 64, (size_t)ML*64},
        ES{oh, 64, (size_t)NTOK*64, 1.f}, 256);

    // 11. residual depthwise conv (tiled)
    conv_add_k<<<dim3(64, BHN), 256>>>(v, w_conv, oh);

    // 12. out projection + residual (BK16 proven config)
    gemm_tc<128,128,64,64,false><<<dim3(4, 128, 1), 128>>>(
        AGather{oh}, BP{w_out, DIM, 0}, EFin{x, b_out, out}, DIM);
}

// round 16
// speedup vs baseline: 1.0308x; 1.0308x over previous
#include <cuda_runtime.h>
#include <cuda_fp16.h>
#include <math.h>
#include <stddef.h>
#include <stdint.h>

#define NHEADS 8
#define DIMH   64
#define NTOK   8192
#define BHN    16
#define ML     256
#define LGRP   32
#define DIM    512

// ---------------- scratch ----------------
__device__ float g_q [BHN*NTOK*DIMH];
__device__ float g_k [BHN*NTOK*DIMH];
__device__ float g_v [BHN*NTOK*DIMH];
__device__ float g_ql[BHN*ML*DIMH];
__device__ float g_kl[BHN*ML*DIMH];
__device__ __half g_attn1h[33554432];  // [bh][8192][256] fp16 softmax weights
__device__ __half g_attn3h[33554432];  // [bh][256][8192] fp16 exp(scores)
__device__ float g_rsp[BHN*ML*64*2];
__device__ float g_rs [BHN*ML];
__device__ float g_a2 [BHN*ML*ML];
__device__ float g_xz [BHN*ML*ML];
__device__ float g_xz2[BHN*ML*ML];
__device__ float g_w  [BHN*ML*ML];
__device__ float g_u  [BHN*ML*ML];
__device__ float g_z  [BHN*ML*ML];
__device__ float g_z2 [BHN*ML*ML];
__device__ float g_t3p[16*BHN*ML*DIMH];
__device__ float g_t3 [BHN*ML*DIMH];
__device__ float g_t2 [BHN*ML*DIMH];
__device__ float g_oh [BHN*NTOK*DIMH];
__device__ int   g_scal[2];

// ---------------- primitives ----------------
__device__ __forceinline__ void mma_tf32(float* d, const unsigned* a, const unsigned* b) {
    asm volatile("mma.sync.aligned.m16n8k8.row.col.f32.tf32.tf32.f32 "
        "{%0,%1,%2,%3}, {%4,%5,%6,%7}, {%8,%9}, {%0,%1,%2,%3};"
        : "+f"(d[0]), "+f"(d[1]), "+f"(d[2]), "+f"(d[3])
        : "r"(a[0]), "r"(a[1]), "r"(a[2]), "r"(a[3]), "r"(b[0]), "r"(b[1]));
}
__device__ __forceinline__ void cp16(uint32_t s, const void* g) {
    asm volatile("cp.async.cg.shared.global [%0], [%1], 16;\n" :: "r"(s), "l"(g));
}
__device__ __forceinline__ void cp_commit() {
    asm volatile("cp.async.commit_group;\n" ::: "memory");
}
__device__ __forceinline__ void cp_wait0() {
    asm volatile("cp.async.wait_group 0;\n" ::: "memory");
}
__device__ __forceinline__ void cp_wait1() {
    asm volatile("cp.async.wait_group 1;\n" ::: "memory");
}
__device__ __forceinline__ uint32_t s2u(const void* p) {
    return (uint32_t)__cvta_generic_to_shared(p);
}
__device__ __forceinline__ unsigned fu(float f) { return __float_as_uint(f); }
__device__ __forceinline__ unsigned h2tf(__half h) { return __float_as_uint(__half2float(h)); }

// ---------------- functors ----------------
struct AP {
    const float* p; int ld; size_t bs;
    __device__ __forceinline__ const void* src(int bz, int r, int k) const {
        return p + (size_t)bz*bs + (size_t)r*ld + k;
    }
};
struct BP {
    const float* p; int ld; size_t bs;
    __device__ __forceinline__ const void* src(int bz, int k, int n) const {
        return p + (size_t)bz*bs + (size_t)k*ld + n;
    }
};
// half-A functors
struct AHSplit {            // a3h [bh][256][8192], bz = bh*16 + split
    const __half* p;
    __device__ __forceinline__ const void* src(int bz, int r, int k) const {
        int bh = bz >> 4, sp = bz & 15;
        return p + ((size_t)bh*ML + r)*NTOK + sp*512 + k;
    }
};
struct AH1 {                // a1h [bh][8192][256]
    const __half* p;
    __device__ __forceinline__ const void* src(int bz, int r, int k) const {
        return p + ((size_t)bz*NTOK + r)*256 + k;
    }
};
struct BSplit {
    const float* p;
    __device__ __forceinline__ const void* src(int bz, int k, int n) const {
        int bh = bz >> 4, sp = bz & 15;
        return p + ((size_t)bh*NTOK + sp*512 + k)*64 + n;
    }
};
struct AGather {
    const float* p;
    __device__ __forceinline__ const void* src(int bz, int r, int k) const {
        int b = r >> 13, t = r & (NTOK-1), head = k >> 6, dd = k & 63;
        return p + (((size_t)(b*8+head))*NTOK + t)*64 + dd;
    }
};
// pinv pair-GEMM
struct APair {
    const float* z; const float* xz;
    __device__ __forceinline__ const void* src(int bz, int r, int k) const {
        const float* base = (bz < 16) ? (z  + (size_t)bz*65536)
                                      : (xz + (size_t)(bz-16)*65536);
        return base + (size_t)r*256 + k;
    }
};
struct BPu {
    const float* u;
    __device__ __forceinline__ const void* src(int bz, int k, int n) const {
        return u + (size_t)(bz & 15)*65536 + (size_t)k*256 + n;
    }
};
struct EPair {
    float* z; float* xzn;
    __device__ __forceinline__ void store(int bz, int r, int c, float v) const {
        float* base = (bz < 16) ? (z   + (size_t)bz*65536)
                                : (xzn + (size_t)(bz-16)*65536);
        base[(size_t)r*256 + c] = 0.25f * v;
    }
};
struct ES {
    float* p; int ld; size_t bs; float scale;
    __device__ __forceinline__ void store(int bz, int r, int c, float v) const {
        p[(size_t)bz*bs + (size_t)r*ld + c] = v*scale;
    }
};
struct EDiag {
    float* p; float alpha;
    __device__ __forceinline__ void store(int bz, int r, int c, float v) const {
        p[(size_t)bz*65536 + (size_t)r*256 + c] = ((r==c)?alpha:0.f) - v;
    }
};
struct EW {
    const float* xz; float* w;
    __device__ __forceinline__ void store(int bz, int r, int c, float v) const {
        size_t o = (size_t)bz*65536 + (size_t)r*256 + c;
        w[o] = ((r==c)?15.f:0.f) - 7.f*xz[o] + v;
    }
};
struct EQKV {
    float* q; float* k; float* v;
    __device__ __forceinline__ void store(int bz, int r, int c, float acc) const {
        int b = r >> 13, t = r & (NTOK-1);
        int which = c >> 9, head = (c >> 6) & 7, dd = c & 63;
        float* dst = (which==0) ? q : ((which==1) ? k : v);
        if (which == 0) acc *= 0.125f;
        dst[(((size_t)(b*8+head))*NTOK + t)*64 + dd] = acc;
    }
};
struct EPart {
    float* p;
    __device__ __forceinline__ void store(int bz, int r, int c, float v) const {
        int bh = bz >> 4, sp = bz & 15;
        p[(((size_t)sp*BHN + bh)*ML + r)*64 + c] = v;
    }
};
struct EFin {
    const float* x; const float* bo; float* out;
    __device__ __forceinline__ void store(int bz, int r, int c, float v) const {
        size_t i = (size_t)r*DIM + c;
        out[i] = x[i] + bo[c] + v;
    }
};

// ---------------- general tf32 tensor-core GEMM, cp.async double-buffered ---
template<int BM, int BN, int WM, int WN, bool BT, class FA, class FB, class FE>
__global__ __launch_bounds__((BM/WM)*(BN/WN)*32)
void gemm_tc(FA fa, FB fb, FE fe, int K) {
    constexpr int NTHR = (BM/WM)*(BN/WN)*32;
    constexpr int LDA = 20;
    constexpr int LDB = BN + 4;
    constexpr int MT = WM/16, NT = WN/8;
    __shared__ float As[2*BM*LDA];
    __shared__ float Bs[2*16*LDB];
    const int tid = threadIdx.x;
    const int wid = tid >> 5, lane = tid & 31;
    const int qd = lane >> 2, tq = lane & 3;
    const int wm = (wid / (BN/WN)) * WM, wn = (wid % (BN/WN)) * WN;
    const int m0 = blockIdx.y * BM, n0 = blockIdx.x * BN, bz = blockIdx.z;
    const uint32_t sA = s2u(As), sB = s2u(Bs);

    float acc[MT][NT][4] = {};

    auto load_tile = [&](int k0, int buf) {
        const uint32_t ab = sA + buf*BM*LDA*4;
#pragma unroll
        for (int i = tid; i < BM*4; i += NTHR) {
            int r = i >> 2, kq = (i & 3) << 2;
            cp16(ab + (r*LDA + kq)*4, fa.src(bz, m0 + r, k0 + kq));
        }
        const uint32_t bb = sB + buf*16*LDB*4;
#pragma unroll
        for (int i = tid; i < BN*4; i += NTHR) {
            int kk = i / (BN/4), nq = (i % (BN/4)) * 4;
            cp16(bb + (kk*LDB + nq)*4, fb.src(bz, k0 + kk, n0 + nq));
        }
        cp_commit();
    };

    load_tile(0, 0);
    const int T = K >> 4;
    for (int t = 0; t < T; t++) {
        if (t + 1 < T) { load_tile((t+1) << 4, (t+1) & 1); cp_wait1(); }
        else           { cp_wait0(); }
        __syncthreads();
        const float* Ab = As + (t & 1)*BM*LDA;
        const float* Bb = Bs + (t & 1)*16*LDB;
#pragma unroll
        for (int ks = 0; ks < 16; ks += 8) {
            unsigned af[MT][4];
#pragma unroll
            for (int mt = 0; mt < MT; mt++) {
                int mm = wm + mt*16 + qd;
                af[mt][0] = fu(Ab[ mm     *LDA + ks + tq    ]);
                af[mt][1] = fu(Ab[(mm + 8)*LDA + ks + tq    ]);
                af[mt][2] = fu(Ab[ mm     *LDA + ks + tq + 4]);
                af[mt][3] = fu(Ab[(mm + 8)*LDA + ks + tq + 4]);
            }
#pragma unroll
            for (int nt = 0; nt < NT; nt++) {
                int nn = wn + nt*8 + qd;
                unsigned bf[2];
                bf[0] = fu(Bb[(ks + tq    )*LDB + nn]);
                bf[1] = fu(Bb[(ks + tq + 4)*LDB + nn]);
#pragma unroll
                for (int mt = 0; mt < MT; mt++)
                    mma_tf32(acc[mt][nt], af[mt], bf);
            }
        }
        __syncthreads();
    }
#pragma unroll
    for (int mt = 0; mt < MT; mt++)
#pragma unroll
        for (int nt = 0; nt < NT; nt++) {
            int r = m0 + wm + mt*16 + qd;
            int c = n0 + wn + nt*8 + tq*2;
            fe.store(bz, r,   c,   acc[mt][nt][0]);
            fe.store(bz, r,   c+1, acc[mt][nt][1]);
            fe.store(bz, r+8, c,   acc[mt][nt][2]);
            fe.store(bz, r+8, c+1, acc[mt][nt][3]);
        }
}

// ------- variant: A operand fp16, B fp32 (tf32 mma) -------------------------
template<int BM, int BN, int WM, int WN, class FA, class FB, class FE>
__global__ __launch_bounds__((BM/WM)*(BN/WN)*32)
void gemm_tc_ha(FA fa, FB fb, FE fe, int K) {
    constexpr int NTHR = (BM/WM)*(BN/WN)*32;
    constexpr int LDAH = 24;
    constexpr int LDB = BN + 4;
    constexpr int MT = WM/16, NT = WN/8;
    __shared__ __half As[2*BM*LDAH];
    __shared__ float  Bs[2*16*LDB];
    const int tid = threadIdx.x;
    const int wid = tid >> 5, lane = tid & 31;
    const int qd = lane >> 2, tq = lane & 3;
    const int wm = (wid / (BN/WN)) * WM, wn = (wid % (BN/WN)) * WN;
    const int m0 = blockIdx.y * BM, n0 = blockIdx.x * BN, bz = blockIdx.z;
    const uint32_t sA = s2u(As), sB = s2u(Bs);

    float acc[MT][NT][4] = {};

    auto load_tile = [&](int k0, int buf) {
        const uint32_t ab = sA + buf*BM*LDAH*2;
#pragma unroll
        for (int i = tid; i < BM*2; i += NTHR) {
            int r = i >> 1, kh = (i & 1) << 3;
            cp16(ab + (r*LDAH + kh)*2, fa.src(bz, m0 + r, k0 + kh));
        }
        const uint32_t bb = sB + buf*16*LDB*4;
#pragma unroll
        for (int i = tid; i < BN*4; i += NTHR) {
            int kk = i / (BN/4), nq = (i % (BN/4)) * 4;
            cp16(bb + (kk*LDB + nq)*4, fb.src(bz, k0 + kk, n0 + nq));
        }
        cp_commit();
    };

    load_tile(0, 0);
    const int T = K >> 4;
    for (int t = 0; t < T; t++) {
        if (t + 1 < T) { load_tile((t+1) << 4, (t+1) & 1); cp_wait1(); }
        else           { cp_wait0(); }
        __syncthreads();
        const __half* Ab = As + (t & 1)*BM*LDAH;
        const float*  Bb = Bs + (t & 1)*16*LDB;
#pragma unroll
        for (int ks = 0; ks < 16; ks += 8) {
            unsigned af[MT][4];
#pragma unroll
            for (int mt = 0; mt < MT; mt++) {
                int mm = wm + mt*16 + qd;
                af[mt][0] = h2tf(Ab[ mm     *LDAH + ks + tq    ]);
                af[mt][1] = h2tf(Ab[(mm + 8)*LDAH + ks + tq    ]);
                af[mt][2] = h2tf(Ab[ mm     *LDAH + ks + tq + 4]);
                af[mt][3] = h2tf(Ab[(mm + 8)*LDAH + ks + tq + 4]);
            }
#pragma unroll
            for (int nt = 0; nt < NT; nt++) {
                int nn = wn + nt*8 + qd;
                unsigned bf[2];
                bf[0] = fu(Bb[(ks + tq    )*LDB + nn]);
                bf[1] = fu(Bb[(ks + tq + 4)*LDB + nn]);
#pragma unroll
                for (int mt = 0; mt < MT; mt++)
                    mma_tf32(acc[mt][nt], af[mt], bf);
            }
        }
        __syncthreads();
    }
#pragma unroll
    for (int mt = 0; mt < MT; mt++)
#pragma unroll
        for (int nt = 0; nt < NT; nt++) {
            int r = m0 + wm + mt*16 + qd;
            int c = n0 + wn + nt*8 + tq*2;
            fe.store(bz, r,   c,   acc[mt][nt][0]);
            fe.store(bz, r,   c+1, acc[mt][nt][1]);
            fe.store(bz, r+8, c,   acc[mt][nt][2]);
            fe.store(bz, r+8, c+1, acc[mt][nt][3]);
        }
}

// ---------------- fused GEMM + row softmax (fp32 B): attn2 -----------------
template<class OutT>
__global__ __launch_bounds__(256)
void gemm_rowsmax(const float* __restrict__ A, size_t a_bs,
                  const float* __restrict__ B, size_t b_bs,
                  OutT* __restrict__ O, size_t o_bs) {
    extern __shared__ float sm[];
    float* As = sm;                 // [2][128][20]
    float* Bs = sm + 2*128*20;      // [256][68]
    const int tid = threadIdx.x, wid = tid >> 5, lane = tid & 31;
    const int qd = lane >> 2, tq = lane & 3;
    const int m0 = blockIdx.y * 128, bz = blockIdx.z;
    const float* Ag = A + (size_t)bz * a_bs;
    const float* Bg = B + (size_t)bz * b_bs;
    const uint32_t sA = s2u(As), sB = s2u(Bs);

#pragma unroll
    for (int i = tid; i < 256*4; i += 256) {
        int n = i >> 2, kq = (i & 3) << 2;
        cp16(sB + (n*68 + kq)*4, Bg + (size_t)n*64 + kq);
    }
#pragma unroll
    for (int i = tid; i < 128*4; i += 256) {
        int r = i >> 2, kq = (i & 3) << 2;
        cp16(sA + (r*20 + kq)*4, Ag + (size_t)(m0 + r)*64 + kq);
    }
    cp_commit();

    float acc[32][4] = {};
    for (int t = 0; t < 4; t++) {
        if (t < 3) {
            const uint32_t ab = sA + ((t+1) & 1)*128*20*4;
            const int k0 = (t+1) << 4;
#pragma unroll
            for (int i = tid; i < 128*4; i += 256) {
                int r = i >> 2, kq = (i & 3) << 2;
                cp16(ab + (r*20 + kq)*4, Ag + (size_t)(m0 + r)*64 + k0 + kq);
            }
            cp_commit();
            cp_wait1();
        } else cp_wait0();
        __syncthreads();
        const float* Ab = As + (t & 1)*128*20;
        const int kb = t << 4;
#pragma unroll
        for (int ks = 0; ks < 16; ks += 8) {
            unsigned af[4];
            int mm = wid*16 + qd;
            af[0] = fu(Ab[ mm     *20 + ks + tq    ]);
            af[1] = fu(Ab[(mm + 8)*20 + ks + tq    ]);
            af[2] = fu(Ab[ mm     *20 + ks + tq + 4]);
            af[3] = fu(Ab[(mm + 8)*20 + ks + tq + 4]);
#pragma unroll
            for (int nt = 0; nt < 32; nt++) {
                int nn = nt*8 + qd;
                unsigned bf[2];
                bf[0] = fu(Bs[nn*68 + kb + ks + tq    ]);
                bf[1] = fu(Bs[nn*68 + kb + ks + tq + 4]);
                mma_tf32(acc[nt], af, bf);
            }
        }
        __syncthreads();
    }
    float mx0 = -1e30f, mx1 = -1e30f;
#pragma unroll
    for (int nt = 0; nt < 32; nt++) {
        mx0 = fmaxf(mx0, fmaxf(acc[nt][0], acc[nt][1]));
        mx1 = fmaxf(mx1, fmaxf(acc[nt][2], acc[nt][3]));
    }
#pragma unroll
    for (int s = 1; s < 4; s <<= 1) {
        mx0 = fmaxf(mx0, __shfl_xor_sync(0xffffffffu, mx0, s));
        mx1 = fmaxf(mx1, __shfl_xor_sync(0xffffffffu, mx1, s));
    }
    float s0 = 0.f, s1 = 0.f;
#pragma unroll
    for (int nt = 0; nt < 32; nt++) {
        acc[nt][0] = __expf(acc[nt][0] - mx0);
        acc[nt][1] = __expf(acc[nt][1] - mx0);
        acc[nt][2] = __expf(acc[nt][2] - mx1);
        acc[nt][3] = __expf(acc[nt][3] - mx1);
        s0 += acc[nt][0] + acc[nt][1];
        s1 += acc[nt][2] + acc[nt][3];
    }
#pragma unroll
    for (int s = 1; s < 4; s <<= 1) {
        s0 += __shfl_xor_sync(0xffffffffu, s0, s);
        s1 += __shfl_xor_sync(0xffffffffu, s1, s);
    }
    const float i0 = 1.f / s0, i1 = 1.f / s1;
    const int r0 = m0 + wid*16 + qd;
    OutT* O0 = O + (size_t)bz*o_bs + (size_t)r0*256;
#pragma unroll
    for (int nt = 0; nt < 32; nt++) {
        int c = nt*8 + tq*2;
        if constexpr (sizeof(OutT) == 4) {
            *(float2*)((float*)O0 + c)         = make_float2(acc[nt][0]*i0, acc[nt][1]*i0);
            *(float2*)((float*)O0 + 8*256 + c) = make_float2(acc[nt][2]*i1, acc[nt][3]*i1);
        } else {
            *(__half2*)((__half*)O0 + c)         = __floats2half2_rn(acc[nt][0]*i0, acc[nt][1]*i0);
            *(__half2*)((__half*)O0 + 8*256 + c) = __floats2half2_rn(acc[nt][2]*i1, acc[nt][3]*i1);
        }
    }
}

// ------ attn1 rowsmax, fp16 B tile in smem (57 KB -> 4 blocks/SM) ----------
__global__ __launch_bounds__(256)
void gemm_rowsmax_h(const float* __restrict__ A, size_t a_bs,
                    const float* __restrict__ B, size_t b_bs,
                    __half* __restrict__ O, size_t o_bs) {
    extern __shared__ float sm[];
    float*  As = sm;                          // [2][128][20] = 20480 B
    __half* Bs = (__half*)(sm + 2*128*20);    // [256][72] halves = 36864 B
    const int tid = threadIdx.x, wid = tid >> 5, lane = tid & 31;
    const int qd = lane >> 2, tq = lane & 3;
    const int m0 = blockIdx.y * 128, bz = blockIdx.z;
    const float* Ag = A + (size_t)bz * a_bs;
    const float* Bg = B + (size_t)bz * b_bs;
    const uint32_t sA = s2u(As);

    // stage B fp32 -> fp16 smem (one-time)
#pragma unroll
    for (int i = tid; i < 256*32; i += 256) {
        int n = i >> 5, cq = (i & 31) * 2;
        float2 vv = *(const float2*)(Bg + (size_t)n*64 + cq);
        *(__half2*)(Bs + n*72 + cq) = __floats2half2_rn(vv.x, vv.y);
    }
#pragma unroll
    for (int i = tid; i < 128*4; i += 256) {
        int r = i >> 2, kq = (i & 3) << 2;
        cp16(sA + (r*20 + kq)*4, Ag + (size_t)(m0 + r)*64 + kq);
    }
    cp_commit();

    float acc[32][4] = {};
    for (int t = 0; t < 4; t++) {
        if (t < 3) {
            const uint32_t ab = sA + ((t+1) & 1)*128*20*4;
            const int k0 = (t+1) << 4;
#pragma unroll
            for (int i = tid; i < 128*4; i += 256) {
                int r = i >> 2, kq = (i & 3) << 2;
                cp16(ab + (r*20 + kq)*4, Ag + (size_t)(m0 + r)*64 + k0 + kq);
            }
            cp_commit();
            cp_wait1();
        } else cp_wait0();
        __syncthreads();   // also orders the one-time B staging on t=0
        const float* Ab = As + (t & 1)*128*20;
        const int kb = t << 4;
#pragma unroll
        for (int ks = 0; ks < 16; ks += 8) {
            unsigned af[4];
            int mm = wid*16 + qd;
            af[0] = fu(Ab[ mm     *20 + ks + tq    ]);
            af[1] = fu(Ab[(mm + 8)*20 + ks + tq    ]);
            af[2] = fu(Ab[ mm     *20 + ks + tq + 4]);
            af[3] = fu(Ab[(mm + 8)*20 + ks + tq + 4]);
#pragma unroll
            for (int nt = 0; nt < 32; nt++) {
                int nn = nt*8 + qd;
                unsigned bf[2];
                bf[0] = h2tf(Bs[nn*72 + kb + ks + tq    ]);
                bf[1] = h2tf(Bs[nn*72 + kb + ks + tq + 4]);
                mma_tf32(acc[nt], af, bf);
            }
        }
        __syncthreads();
    }
    float mx0 = -1e30f, mx1 = -1e30f;
#pragma unroll
    for (int nt = 0; nt < 32; nt++) {
        mx0 = fmaxf(mx0, fmaxf(acc[nt][0], acc[nt][1]));
        mx1 = fmaxf(mx1, fmaxf(acc[nt][2], acc[nt][3]));
    }
#pragma unroll
    for (int s = 1; s < 4; s <<= 1) {
        mx0 = fmaxf(mx0, __shfl_xor_sync(0xffffffffu, mx0, s));
        mx1 = fmaxf(mx1, __shfl_xor_sync(0xffffffffu, mx1, s));
    }
    float s0 = 0.f, s1 = 0.f;
#pragma unroll
    for (int nt = 0; nt < 32; nt++) {
        acc[nt][0] = __expf(acc[nt][0] - mx0);
        acc[nt][1] = __expf(acc[nt][1] - mx0);
        acc[nt][2] = __expf(acc[nt][2] - mx1);
        acc[nt][3] = __expf(acc[nt][3] - mx1);
        s0 += acc[nt][0] + acc[nt][1];
        s1 += acc[nt][2] + acc[nt][3];
    }
#pragma unroll
    for (int s = 1; s < 4; s <<= 1) {
        s0 += __shfl_xor_sync(0xffffffffu, s0, s);
        s1 += __shfl_xor_sync(0xffffffffu, s1, s);
    }
    const float i0 = 1.f / s0, i1 = 1.f / s1;
    const int r0 = m0 + wid*16 + qd;
    __half* O0 = O + (size_t)bz*o_bs + (size_t)r0*256;
#pragma unroll
    for (int nt = 0; nt < 32; nt++) {
        int c = nt*8 + tq*2;
        *(__half2*)(O0 + c)         = __floats2half2_rn(acc[nt][0]*i0, acc[nt][1]*i0);
        *(__half2*)(O0 + 8*256 + c) = __floats2half2_rn(acc[nt][2]*i1, acc[nt][3]*i1);
    }
}

// ------- sim3 with fused exp (fp16 store) + fp32 row-sum partials -----------
__global__ __launch_bounds__(128)
void sim3_exp_k(const float* __restrict__ QL, const float* __restrict__ Kg,
                __half* __restrict__ A3, float* __restrict__ RSP) {
    constexpr int LDA = 20;
    __shared__ float As[2*128*LDA];
    __shared__ float Bs[2*128*LDA];
    const int tid = threadIdx.x;
    const int wid = tid >> 5, lane = tid & 31;
    const int qd = lane >> 2, tq = lane & 3;
    const int wm = (wid >> 1) * 64, wn = (wid & 1) * 64;
    const int n0 = blockIdx.x * 128, m0 = blockIdx.y * 128;
    const int bz = blockIdx.z;
    const float* Ag = QL + (size_t)bz * ML * 64;
    const float* Bg = Kg + (size_t)bz * NTOK * 64;
    const uint32_t sA = s2u(As), sB = s2u(Bs);

    float acc[4][8][4] = {};
    auto load_tile = [&](int k0, int buf) {
        const uint32_t ab = sA + buf*128*LDA*4;
#pragma unroll
        for (int i = tid; i < 128*4; i += 128) {
            int r = i >> 2, kq = (i & 3) << 2;
            cp16(ab + (r*LDA + kq)*4, Ag + (size_t)(m0 + r)*64 + k0 + kq);
        }
        const uint32_t bb = s2u(Bs) + buf*128*LDA*4;
#pragma unroll
        for (int i = tid; i < 128*4; i += 128) {
            int n = i >> 2, kq = (i & 3) << 2;
            cp16(bb + (n*LDA + kq)*4, Bg + (size_t)(n0 + n)*64 + k0 + kq);
        }
        cp_commit();
    };

    load_tile(0, 0);
    for (int t = 0; t < 4; t++) {
        if (t + 1 < 4) { load_tile((t+1) << 4, (t+1) & 1); cp_wait1(); }
        else           { cp_wait0(); }
        __syncthreads();
        const float* Ab = As + (t & 1)*128*LDA;
        const float* Bb = Bs + (t & 1)*128*LDA;
#pragma unroll
        for (int ks = 0; ks < 16; ks += 8) {
            unsigned af[4][4];
#pragma unroll
            for (int mt = 0; mt < 4; mt++) {
                int mm = wm + mt*16 + qd;
                af[mt][0] = fu(Ab[ mm     *LDA + ks + tq    ]);
                af[mt][1] = fu(Ab[(mm + 8)*LDA + ks + tq    ]);
                af[mt][2] = fu(Ab[ mm     *LDA + ks + tq + 4]);
                af[mt][3] = fu(Ab[(mm + 8)*LDA + ks + tq + 4]);
            }
#pragma unroll
            for (int nt = 0; nt < 8; nt++) {
                int nn = wn + nt*8 + qd;
                unsigned bf[2];
                bf[0] = fu(Bb[nn*LDA + ks + tq    ]);
                bf[1] = fu(Bb[nn*LDA + ks + tq + 4]);
#pragma unroll
                for (int mt = 0; mt < 4; mt++)
                    mma_tf32(acc[mt][nt], af[mt], bf);
            }
        }
        __syncthreads();
    }

    __half* a3b = A3 + (size_t)bz * ML * NTOK;
    const int wh = wid & 1;
#pragma unroll
    for (int mt = 0; mt < 4; mt++) {
        const int r = wm + mt*16 + qd;
        float slo = 0.f, shi = 0.f;
#pragma unroll
        for (int nt = 0; nt < 8; nt++) {
            int c = n0 + wn + nt*8 + tq*2;
            float e0 = __expf(acc[mt][nt][0]);
            float e1 = __expf(acc[mt][nt][1]);
            float e2 = __expf(acc[mt][nt][2]);
            float e3 = __expf(acc[mt][nt][3]);
            *(__half2*)(a3b + (size_t)(m0 + r    )*NTOK + c) = __floats2half2_rn(e0, e1);
            *(__half2*)(a3b + (size_t)(m0 + r + 8)*NTOK + c) = __floats2half2_rn(e2, e3);
            slo += e0 + e1;
            shi += e2 + e3;
        }
#pragma unroll
        for (int s = 1; s < 4; s <<= 1) {
            slo += __shfl_xor_sync(0xffffffffu, slo, s);
            shi += __shfl_xor_sync(0xffffffffu, shi, s);
        }
        if (tq == 0) {
            RSP[(((size_t)bz*ML + (m0 + r    ))*64 + blockIdx.x)*2 + wh] = slo;
            RSP[(((size_t)bz*ML + (m0 + r + 8))*64 + blockIdx.x)*2 + wh] = shi;
        }
    }
}

__global__ __launch_bounds__(256)
void rowsum_k(const float* __restrict__ rsp, float* __restrict__ rs) {
    int row = blockIdx.x * 8 + (threadIdx.x >> 5);
    int lane = threadIdx.x & 31;
    const float* p = rsp + (size_t)row * 128;
    float s = p[lane] + p[lane + 32] + p[lane + 64] + p[lane + 96];
#pragma unroll
    for (int sh = 16; sh > 0; sh >>= 1) s += __shfl_xor_sync(0xffffffffu, s, sh);
    if (lane == 0) rs[row] = s;
}

// ---------------- small kernels ----------------
__global__ void init_scal_k(int* scal) { if (threadIdx.x < 2) scal[threadIdx.x] = 0; }

__global__ __launch_bounds__(256) void landmarks_k(
        const float* __restrict__ q, const float* __restrict__ k,
        float* __restrict__ ql, float* __restrict__ kl) {
    int idx = blockIdx.x * 256 + threadIdx.x;
    int dd = idx & 63, j = (idx >> 6) & 255, bh = idx >> 14;
    const float* qp = q + ((size_t)bh*NTOK + (size_t)j*LGRP)*64 + dd;
    const float* kp = k + ((size_t)bh*NTOK + (size_t)j*LGRP)*64 + dd;
    float sq = 0.f, sk = 0.f;
#pragma unroll
    for (int t = 0; t < LGRP; t++) { sq += qp[(size_t)t*64]; sk += kp[(size_t)t*64]; }
    ql[idx] = sq * (1.f/LGRP);
    kl[idx] = sk * (1.f/LGRP);
}

__global__ __launch_bounds__(256) void scal_reduce_k(const float* __restrict__ a2, int* scal) {
    int idx = blockIdx.x, bh = blockIdx.y, mode = blockIdx.z, tid = threadIdx.x;
    const float* base = a2 + (size_t)bh * 65536;
    float v = (mode == 0) ? base[(size_t)idx*256 + tid] : base[(size_t)tid*256 + idx];
    __shared__ float red[256];
    red[tid] = v; __syncthreads();
    for (int s = 128; s > 0; s >>= 1) { if (tid < s) red[tid] += red[tid+s]; __syncthreads(); }
    if (tid == 0) atomicMax(&scal[mode], __float_as_int(red[0]));
}

__global__ __launch_bounds__(256) void zinit_k(const float* __restrict__ a2,
                                               const int* __restrict__ scal,
                                               float* __restrict__ z) {
    size_t idx = (size_t)blockIdx.x * 256 + threadIdx.x;
    float col = __int_as_float(scal[0]), row = __int_as_float(scal[1]);
    float rcp = 1.f / (col * row);
    int j = (int)(idx & 255), i = (int)((idx >> 8) & 255);
    size_t bh = idx >> 16;
    z[idx] = a2[(bh << 16) + (size_t)j*256 + i] * rcp;
}

__global__ __launch_bounds__(256) void t3_reduce_k(const float* __restrict__ part,
                                                   const float* __restrict__ rs,
                                                   float* __restrict__ t3) {
    int idx = blockIdx.x * 256 + threadIdx.x;
    float s = 0.f;
#pragma unroll
    for (int sp = 0; sp < 16; sp++) s += part[(size_t)sp*262144 + idx];
    t3[idx] = s / rs[idx >> 6];
}

// -------- tiled depthwise conv ----------
__global__ __launch_bounds__(256) void conv_add_k(const float* __restrict__ v,
                                                  const float* __restrict__ wc,
                                                  float* __restrict__ oh) {
    __shared__ float vt[160*64];
    const int chunk = blockIdx.x, bh = blockIdx.y;
    const int h = bh & 7;
    const int tid = threadIdx.x;
    const float* vb = v + (size_t)bh * NTOK * 64;
    const int base = chunk * 128 - 16;

    for (int idx = tid; idx < 160*64; idx += 256) {
        int row = idx >> 6, dd = idx & 63;
        int src = base + row;
        vt[idx] = (src >= 0 && src < NTOK) ? vb[(size_t)src*64 + dd] : 0.f;
    }
    float wreg[33];
#pragma unroll
    for (int t = 0; t < 33; t++) wreg[t] = wc[h*33 + t];
    __syncthreads();

    const int dd = tid & 63, quarter = tid >> 6;
    float vr[64];
#pragma unroll
    for (int x = 0; x < 64; x++) vr[x] = vt[(quarter*32 + x)*64 + dd];

    float* ohb = oh + ((size_t)bh*NTOK + (size_t)chunk*128 + quarter*32)*64 + dd;
#pragma unroll
    for (int j = 0; j < 32; j++) {
        float s = 0.f;
#pragma unroll
        for (int t = 0; t < 33; t++) s += wreg[t] * vr[j + t];
        ohb[(size_t)j*64] += s;
    }
}

// ---------------- orchestration ----------------
extern "C" void kernel_launch(void* const* d_in, const int* in_sizes, int n_in,
                              void* d_out, int out_size) {
    (void)in_sizes; (void)n_in; (void)out_size;
    const float* x      = (const float*)d_in[0];
    const float* w_qkv  = (const float*)d_in[1];
    const float* w_out  = (const float*)d_in[2];
    const float* b_out  = (const float*)d_in[3];
    const float* w_conv = (const float*)d_in[4];
    float* out = (float*)d_out;

    float *q,*k,*v,*ql,*kl,*rsp,*rs,*a2,*xz,*xz2,*w,*u,*z,*z2,*t3p,*t3,*t2,*oh;
    __half *a1h, *a3h;
    int* scal;
    cudaGetSymbolAddress((void**)&q,  g_q);
    cudaGetSymbolAddress((void**)&k,  g_k);
    cudaGetSymbolAddress((void**)&v,  g_v);
    cudaGetSymbolAddress((void**)&ql, g_ql);
    cudaGetSymbolAddress((void**)&kl, g_kl);
    cudaGetSymbolAddress((void**)&a1h,g_attn1h);
    cudaGetSymbolAddress((void**)&a3h,g_attn3h);
    cudaGetSymbolAddress((void**)&rsp,g_rsp);
    cudaGetSymbolAddress((void**)&rs, g_rs);
    cudaGetSymbolAddress((void**)&a2, g_a2);
    cudaGetSymbolAddress((void**)&xz, g_xz);
    cudaGetSymbolAddress((void**)&xz2,g_xz2);
    cudaGetSymbolAddress((void**)&w,  g_w);
    cudaGetSymbolAddress((void**)&u,  g_u);
    cudaGetSymbolAddress((void**)&z,  g_z);
    cudaGetSymbolAddress((void**)&z2, g_z2);
    cudaGetSymbolAddress((void**)&t3p,g_t3p);
    cudaGetSymbolAddress((void**)&t3, g_t3);
    cudaGetSymbolAddress((void**)&t2, g_t2);
    cudaGetSymbolAddress((void**)&oh, g_oh);
    cudaGetSymbolAddress((void**)&scal, g_scal);

    static bool attr_done = false;
    if (!attr_done) {
        cudaFuncSetAttribute(gemm_rowsmax<float>,
            cudaFuncAttributeMaxDynamicSharedMemorySize, 90112);
        cudaFuncSetAttribute(gemm_rowsmax_h,
            cudaFuncAttributeMaxDynamicSharedMemorySize, 57344);
        attr_done = true;
    }

    init_scal_k<<<1, 32>>>(scal);

    // 1. QKV projection
    gemm_tc<128,128,64,64,false><<<dim3(12, 128, 1), 128>>>(
        AP{x, DIM, 0}, BP{w_qkv, 1536, 0}, EQKV{q, k, v}, DIM);

    // 2. landmark means
    landmarks_k<<<1024, 256>>>(q, k, ql, kl);

    // 3. attn2 = softmax(ql @ kl^T), fused (fp32 — feeds pinv)
    gemm_rowsmax<float><<<dim3(1, 2, BHN), 256, 90112>>>(
        ql, (size_t)ML*64, kl, (size_t)ML*64, a2, (size_t)ML*256);

    // 4. pinv init
    scal_reduce_k<<<dim3(256, BHN, 2), 256>>>(a2, scal);
    zinit_k<<<4096, 256>>>(a2, scal, z);

    // 5. Newton–Schulz x6, 3 GEMMs/iter
    float* xzc = xz;
    float* xzn = xz2;
    gemm_tc<64,64,32,32,false><<<dim3(4,4,BHN), 128>>>(
        AP{a2,256,65536}, BP{z,256,65536}, ES{xzc,256,65536,1.f}, 256);
    for (int it = 0; it < 6; it++) {
        float* zin  = (it & 1) ? z2 : z;
        float* zout = (it & 1) ? z  : z2;
        gemm_tc<64,64,32,32,false><<<dim3(4,4,BHN), 128>>>(
            AP{xzc,256,65536}, BP{xzc,256,65536}, EW{xzc, w}, 256);
        gemm_tc<64,64,32,32,false><<<dim3(4,4,BHN), 128>>>(
            AP{xzc,256,65536}, BP{w,256,65536}, EDiag{u,13.f}, 256);
        if (it < 5) {
            gemm_tc<64,64,32,32,false><<<dim3(4,4,2*BHN), 128>>>(
                APair{zin, xzc}, BPu{u}, EPair{zout, xzn}, 256);
            float* tmp = xzc; xzc = xzn; xzn = tmp;
        } else {
            gemm_tc<64,64,32,32,false><<<dim3(4,4,BHN), 128>>>(
                AP{zin,256,65536}, BP{u,256,65536}, ES{zout,256,65536,0.25f}, 256);
        }
    }
    // final z in g_z

    // 6. attn1 = softmax(q @ kl^T) -> fp16 (fp16-B smem, 4 blocks/SM)
    gemm_rowsmax_h<<<dim3(1, 64, BHN), 256, 57344>>>(
        q, (size_t)NTOK*64, kl, (size_t)ML*64, a1h, (size_t)NTOK*256);

    // 7. a3 = exp(ql @ k^T) -> fp16, fp32 row-sum partials
    sim3_exp_k<<<dim3(64, 2, BHN), 128>>>(ql, k, a3h, rsp);
    rowsum_k<<<512, 256>>>(rsp, rs);

    // 8. t3 = (exp-scores @ v) / rowsum  (half-A split-K x16)
    gemm_tc_ha<128,64,64,32><<<dim3(1, 2, BHN*16), 128>>>(
        AHSplit{a3h}, BSplit{v}, EPart{t3p}, 512);
    t3_reduce_k<<<1024, 256>>>(t3p, rs, t3);

    // 9. t2 = z @ t3
    gemm_tc<128,64,64,32,false><<<dim3(1, 2, BHN), 128>>>(
        AP{z, 256, 65536}, BP{t3, 64, (size_t)ML*64},
        ES{t2, 64, (size_t)ML*64, 1.f}, 256);

    // 10. oh = attn1 @ t2  (half-A, fp32 B)
    gemm_tc_ha<128,64,64,32><<<dim3(1, 64, BHN), 128>>>(
        AH1{a1h}, BP{t2, 64, (size_t)ML*64},
        ES{oh, 64, (size_t)NTOK*64, 1.f}, 256);

    // 11. residual depthwise conv (tiled)
    conv_add_k<<<dim3(64, BHN), 256>>>(v, w_conv, oh);

    // 12. out projection + residual
    gemm_tc<128,128,64,64,false><<<dim3(4, 128, 1), 128>>>(
        AGather{oh}, BP{w_out, DIM, 0}, EFin{x, b_out, out}, DIM);
}

// round 17
// speedup vs baseline: 1.0452x; 1.0140x over previous
#include <cuda_runtime.h>
#include <cuda_fp16.h>
#include <math.h>
#include <stddef.h>
#include <stdint.h>

#define NHEADS 8
#define DIMH   64
#define NTOK   8192
#define BHN    16
#define ML     256
#define LGRP   32
#define DIM    512

// ---------------- scratch ----------------
__device__ float g_q [BHN*NTOK*DIMH];
__device__ float g_k [BHN*NTOK*DIMH];
__device__ float g_v [BHN*NTOK*DIMH];
__device__ __half g_vhT[BHN*DIMH*NTOK];  // fp16 v transposed [bh][dd][t]
__device__ float g_ql[BHN*ML*DIMH];
__device__ float g_kl[BHN*ML*DIMH];
__device__ __half g_attn1h[33554432];  // [bh][8192][256]
__device__ __half g_attn3h[33554432];  // [bh][256][8192]
__device__ float g_rsp[BHN*ML*64*2];
__device__ float g_rs [BHN*ML];
__device__ float g_a2 [BHN*ML*ML];
__device__ float g_xz [BHN*ML*ML];
__device__ float g_xz2[BHN*ML*ML];
__device__ float g_w  [BHN*ML*ML];
__device__ float g_u  [BHN*ML*ML];
__device__ float g_z  [BHN*ML*ML];
__device__ float g_z2 [BHN*ML*ML];
__device__ float g_t3p[16*BHN*ML*DIMH];
__device__ float g_t3 [BHN*ML*DIMH];
__device__ __half g_t2h[BHN*DIMH*ML];    // t2 transposed fp16 [bh][dd][m]
__device__ float g_oh [BHN*NTOK*DIMH];
__device__ int   g_scal[2];

// ---------------- primitives ----------------
__device__ __forceinline__ void mma_tf32(float* d, const unsigned* a, const unsigned* b) {
    asm volatile("mma.sync.aligned.m16n8k8.row.col.f32.tf32.tf32.f32 "
        "{%0,%1,%2,%3}, {%4,%5,%6,%7}, {%8,%9}, {%0,%1,%2,%3};"
        : "+f"(d[0]), "+f"(d[1]), "+f"(d[2]), "+f"(d[3])
        : "r"(a[0]), "r"(a[1]), "r"(a[2]), "r"(a[3]), "r"(b[0]), "r"(b[1]));
}
__device__ __forceinline__ void mma_f16(float* d, const unsigned* a, const unsigned* b) {
    asm volatile("mma.sync.aligned.m16n8k16.row.col.f32.f16.f16.f32 "
        "{%0,%1,%2,%3}, {%4,%5,%6,%7}, {%8,%9}, {%0,%1,%2,%3};"
        : "+f"(d[0]), "+f"(d[1]), "+f"(d[2]), "+f"(d[3])
        : "r"(a[0]), "r"(a[1]), "r"(a[2]), "r"(a[3]), "r"(b[0]), "r"(b[1]));
}
__device__ __forceinline__ void cp16(uint32_t s, const void* g) {
    asm volatile("cp.async.cg.shared.global [%0], [%1], 16;\n" :: "r"(s), "l"(g));
}
__device__ __forceinline__ void cp_commit() {
    asm volatile("cp.async.commit_group;\n" ::: "memory");
}
__device__ __forceinline__ void cp_wait0() {
    asm volatile("cp.async.wait_group 0;\n" ::: "memory");
}
__device__ __forceinline__ void cp_wait1() {
    asm volatile("cp.async.wait_group 1;\n" ::: "memory");
}
__device__ __forceinline__ uint32_t s2u(const void* p) {
    return (uint32_t)__cvta_generic_to_shared(p);
}
__device__ __forceinline__ unsigned fu(float f) { return __float_as_uint(f); }

// ---------------- functors ----------------
struct AP {
    const float* p; int ld; size_t bs;
    __device__ __forceinline__ const void* src(int bz, int r, int k) const {
        return p + (size_t)bz*bs + (size_t)r*ld + k;
    }
};
struct BP {
    const float* p; int ld; size_t bs;
    __device__ __forceinline__ const void* src(int bz, int k, int n) const {
        return p + (size_t)bz*bs + (size_t)k*ld + n;
    }
};
struct AHSplit {            // a3h [bh][256][8192], bz = bh*16 + split
    const __half* p;
    __device__ __forceinline__ const void* src(int bz, int r, int k) const {
        int bh = bz >> 4, sp = bz & 15;
        return p + ((size_t)bh*ML + r)*NTOK + sp*512 + k;
    }
};
struct AH1 {                // a1h [bh][8192][256]
    const __half* p;
    __device__ __forceinline__ const void* src(int bz, int r, int k) const {
        return p + ((size_t)bz*NTOK + r)*256 + k;
    }
};
struct BTv {                // vhT [bh][64][8192], bz = bh*16 + split; n-major, k-contig
    const __half* p;
    __device__ __forceinline__ const void* src(int bz, int n, int k) const {
        int bh = bz >> 4, sp = bz & 15;
        return p + ((size_t)bh*64 + n)*NTOK + sp*512 + k;
    }
};
struct BTt2 {               // t2hT [bh][64][256]
    const __half* p;
    __device__ __forceinline__ const void* src(int bz, int n, int k) const {
        return p + ((size_t)bz*64 + n)*256 + k;
    }
};
struct AGather {
    const float* p;
    __device__ __forceinline__ const void* src(int bz, int r, int k) const {
        int b = r >> 13, t = r & (NTOK-1), head = k >> 6, dd = k & 63;
        return p + (((size_t)(b*8+head))*NTOK + t)*64 + dd;
    }
};
struct APair {
    const float* z; const float* xz;
    __device__ __forceinline__ const void* src(int bz, int r, int k) const {
        const float* base = (bz < 16) ? (z  + (size_t)bz*65536)
                                      : (xz + (size_t)(bz-16)*65536);
        return base + (size_t)r*256 + k;
    }
};
struct BPu {
    const float* u;
    __device__ __forceinline__ const void* src(int bz, int k, int n) const {
        return u + (size_t)(bz & 15)*65536 + (size_t)k*256 + n;
    }
};
struct EPair {
    float* z; float* xzn;
    __device__ __forceinline__ void store(int bz, int r, int c, float v) const {
        float* base = (bz < 16) ? (z   + (size_t)bz*65536)
                                : (xzn + (size_t)(bz-16)*65536);
        base[(size_t)r*256 + c] = 0.25f * v;
    }
};
struct ES {
    float* p; int ld; size_t bs; float scale;
    __device__ __forceinline__ void store(int bz, int r, int c, float v) const {
        p[(size_t)bz*bs + (size_t)r*ld + c] = v*scale;
    }
};
struct EST2 {               // write t2 transposed as fp16
    __half* p;
    __device__ __forceinline__ void store(int bz, int r, int c, float v) const {
        p[((size_t)bz*64 + c)*256 + r] = __float2half_rn(v);
    }
};
struct EDiag {
    float* p; float alpha;
    __device__ __forceinline__ void store(int bz, int r, int c, float v) const {
        p[(size_t)bz*65536 + (size_t)r*256 + c] = ((r==c)?alpha:0.f) - v;
    }
};
struct EW {
    const float* xz; float* w;
    __device__ __forceinline__ void store(int bz, int r, int c, float v) const {
        size_t o = (size_t)bz*65536 + (size_t)r*256 + c;
        w[o] = ((r==c)?15.f:0.f) - 7.f*xz[o] + v;
    }
};
struct EQKV {
    float* q; float* k; float* v;
    __device__ __forceinline__ void store(int bz, int r, int c, float acc) const {
        int b = r >> 13, t = r & (NTOK-1);
        int which = c >> 9, head = (c >> 6) & 7, dd = c & 63;
        float* dst = (which==0) ? q : ((which==1) ? k : v);
        if (which == 0) acc *= 0.125f;
        dst[(((size_t)(b*8+head))*NTOK + t)*64 + dd] = acc;
    }
};
struct EPart {
    float* p;
    __device__ __forceinline__ void store(int bz, int r, int c, float v) const {
        int bh = bz >> 4, sp = bz & 15;
        p[(((size_t)sp*BHN + bh)*ML + r)*64 + c] = v;
    }
};
struct EFin {
    const float* x; const float* bo; float* out;
    __device__ __forceinline__ void store(int bz, int r, int c, float v) const {
        size_t i = (size_t)r*DIM + c;
        out[i] = x[i] + bo[c] + v;
    }
};

// ---------------- general tf32 tensor-core GEMM, cp.async double-buffered ---
template<int BM, int BN, int WM, int WN, class FA, class FB, class FE>
__global__ __launch_bounds__((BM/WM)*(BN/WN)*32)
void gemm_tc(FA fa, FB fb, FE fe, int K) {
    constexpr int NTHR = (BM/WM)*(BN/WN)*32;
    constexpr int LDA = 20;
    constexpr int LDB = BN + 4;
    constexpr int MT = WM/16, NT = WN/8;
    __shared__ float As[2*BM*LDA];
    __shared__ float Bs[2*16*LDB];
    const int tid = threadIdx.x;
    const int wid = tid >> 5, lane = tid & 31;
    const int qd = lane >> 2, tq = lane & 3;
    const int wm = (wid / (BN/WN)) * WM, wn = (wid % (BN/WN)) * WN;
    const int m0 = blockIdx.y * BM, n0 = blockIdx.x * BN, bz = blockIdx.z;
    const uint32_t sA = s2u(As), sB = s2u(Bs);

    float acc[MT][NT][4] = {};

    auto load_tile = [&](int k0, int buf) {
        const uint32_t ab = sA + buf*BM*LDA*4;
#pragma unroll
        for (int i = tid; i < BM*4; i += NTHR) {
            int r = i >> 2, kq = (i & 3) << 2;
            cp16(ab + (r*LDA + kq)*4, fa.src(bz, m0 + r, k0 + kq));
        }
        const uint32_t bb = sB + buf*16*LDB*4;
#pragma unroll
        for (int i = tid; i < BN*4; i += NTHR) {
            int kk = i / (BN/4), nq = (i % (BN/4)) * 4;
            cp16(bb + (kk*LDB + nq)*4, fb.src(bz, k0 + kk, n0 + nq));
        }
        cp_commit();
    };

    load_tile(0, 0);
    const int T = K >> 4;
    for (int t = 0; t < T; t++) {
        if (t + 1 < T) { load_tile((t+1) << 4, (t+1) & 1); cp_wait1(); }
        else           { cp_wait0(); }
        __syncthreads();
        const float* Ab = As + (t & 1)*BM*LDA;
        const float* Bb = Bs + (t & 1)*16*LDB;
#pragma unroll
        for (int ks = 0; ks < 16; ks += 8) {
            unsigned af[MT][4];
#pragma unroll
            for (int mt = 0; mt < MT; mt++) {
                int mm = wm + mt*16 + qd;
                af[mt][0] = fu(Ab[ mm     *LDA + ks + tq    ]);
                af[mt][1] = fu(Ab[(mm + 8)*LDA + ks + tq    ]);
                af[mt][2] = fu(Ab[ mm     *LDA + ks + tq + 4]);
                af[mt][3] = fu(Ab[(mm + 8)*LDA + ks + tq + 4]);
            }
#pragma unroll
            for (int nt = 0; nt < NT; nt++) {
                int nn = wn + nt*8 + qd;
                unsigned bf[2];
                bf[0] = fu(Bb[(ks + tq    )*LDB + nn]);
                bf[1] = fu(Bb[(ks + tq + 4)*LDB + nn]);
#pragma unroll
                for (int mt = 0; mt < MT; mt++)
                    mma_tf32(acc[mt][nt], af[mt], bf);
            }
        }
        __syncthreads();
    }
#pragma unroll
    for (int mt = 0; mt < MT; mt++)
#pragma unroll
        for (int nt = 0; nt < NT; nt++) {
            int r = m0 + wm + mt*16 + qd;
            int c = n0 + wn + nt*8 + tq*2;
            fe.store(bz, r,   c,   acc[mt][nt][0]);
            fe.store(bz, r,   c+1, acc[mt][nt][1]);
            fe.store(bz, r+8, c,   acc[mt][nt][2]);
            fe.store(bz, r+8, c+1, acc[mt][nt][3]);
        }
}

// ---- fp16 x fp16 HMMA (m16n8k16), A row-k-major, B col-k-major smem -------
template<int BM, int BN, int WM, int WN, class FA, class FB, class FE>
__global__ __launch_bounds__((BM/WM)*(BN/WN)*32)
void gemm_hh2(FA fa, FB fb, FE fe, int K) {
    constexpr int NTHR = (BM/WM)*(BN/WN)*32;
    constexpr int LDK = 24;    // halves per row: 16 data + 8 pad
    constexpr int MT = WM/16, NT = WN/8;
    __shared__ __half As[2*BM*LDK];
    __shared__ __half Bs[2*BN*LDK];
    const int tid = threadIdx.x;
    const int wid = tid >> 5, lane = tid & 31;
    const int qd = lane >> 2, tq = lane & 3;
    const int wm = (wid / (BN/WN)) * WM, wn = (wid % (BN/WN)) * WN;
    const int m0 = blockIdx.y * BM, n0 = blockIdx.x * BN, bz = blockIdx.z;
    const uint32_t sA = s2u(As), sB = s2u(Bs);

    float acc[MT][NT][4] = {};

    auto load_tile = [&](int k0, int buf) {
        const uint32_t ab = sA + buf*BM*LDK*2;
#pragma unroll
        for (int i = tid; i < BM*2; i += NTHR) {
            int r = i >> 1, kh = (i & 1) << 3;
            cp16(ab + (r*LDK + kh)*2, fa.src(bz, m0 + r, k0 + kh));
        }
        const uint32_t bb = sB + buf*BN*LDK*2;
#pragma unroll
        for (int i = tid; i < BN*2; i += NTHR) {
            int n = i >> 1, kh = (i & 1) << 3;
            cp16(bb + (n*LDK + kh)*2, fb.src(bz, n0 + n, k0 + kh));
        }
        cp_commit();
    };

    load_tile(0, 0);
    const int T = K >> 4;
    for (int t = 0; t < T; t++) {
        if (t + 1 < T) { load_tile((t+1) << 4, (t+1) & 1); cp_wait1(); }
        else           { cp_wait0(); }
        __syncthreads();
        const __half* Ab = As + (t & 1)*BM*LDK;
        const __half* Bb = Bs + (t & 1)*BN*LDK;
        unsigned af[MT][4];
#pragma unroll
        for (int mt = 0; mt < MT; mt++) {
            int mm = wm + mt*16 + qd;
            af[mt][0] = *(const unsigned*)(Ab +  mm     *LDK + 2*tq    );
            af[mt][1] = *(const unsigned*)(Ab + (mm + 8)*LDK + 2*tq    );
            af[mt][2] = *(const unsigned*)(Ab +  mm     *LDK + 2*tq + 8);
            af[mt][3] = *(const unsigned*)(Ab + (mm + 8)*LDK + 2*tq + 8);
        }
#pragma unroll
        for (int nt = 0; nt < NT; nt++) {
            int nn = wn + nt*8 + qd;
            unsigned bf[2];
            bf[0] = *(const unsigned*)(Bb + nn*LDK + 2*tq    );
            bf[1] = *(const unsigned*)(Bb + nn*LDK + 2*tq + 8);
#pragma unroll
            for (int mt = 0; mt < MT; mt++)
                mma_f16(acc[mt][nt], af[mt], bf);
        }
        __syncthreads();
    }
#pragma unroll
    for (int mt = 0; mt < MT; mt++)
#pragma unroll
        for (int nt = 0; nt < NT; nt++) {
            int r = m0 + wm + mt*16 + qd;
            int c = n0 + wn + nt*8 + tq*2;
            fe.store(bz, r,   c,   acc[mt][nt][0]);
            fe.store(bz, r,   c+1, acc[mt][nt][1]);
            fe.store(bz, r+8, c,   acc[mt][nt][2]);
            fe.store(bz, r+8, c+1, acc[mt][nt][3]);
        }
}

// ---------------- fused GEMM + row softmax: O = softmax(A @ B^T) -----------
template<class OutT>
__global__ __launch_bounds__(256)
void gemm_rowsmax(const float* __restrict__ A, size_t a_bs,
                  const float* __restrict__ B, size_t b_bs,
                  OutT* __restrict__ O, size_t o_bs) {
    extern __shared__ float sm[];
    float* As = sm;                 // [2][128][20]
    float* Bs = sm + 2*128*20;      // [256][68]
    const int tid = threadIdx.x, wid = tid >> 5, lane = tid & 31;
    const int qd = lane >> 2, tq = lane & 3;
    const int m0 = blockIdx.y * 128, bz = blockIdx.z;
    const float* Ag = A + (size_t)bz * a_bs;
    const float* Bg = B + (size_t)bz * b_bs;
    const uint32_t sA = s2u(As), sB = s2u(Bs);

#pragma unroll
    for (int i = tid; i < 256*4; i += 256) {
        int n = i >> 2, kq = (i & 3) << 2;
        cp16(sB + (n*68 + kq)*4, Bg + (size_t)n*64 + kq);
    }
#pragma unroll
    for (int i = tid; i < 128*4; i += 256) {
        int r = i >> 2, kq = (i & 3) << 2;
        cp16(sA + (r*20 + kq)*4, Ag + (size_t)(m0 + r)*64 + kq);
    }
    cp_commit();

    float acc[32][4] = {};
    for (int t = 0; t < 4; t++) {
        if (t < 3) {
            const uint32_t ab = sA + ((t+1) & 1)*128*20*4;
            const int k0 = (t+1) << 4;
#pragma unroll
            for (int i = tid; i < 128*4; i += 256) {
                int r = i >> 2, kq = (i & 3) << 2;
                cp16(ab + (r*20 + kq)*4, Ag + (size_t)(m0 + r)*64 + k0 + kq);
            }
            cp_commit();
            cp_wait1();
        } else cp_wait0();
        __syncthreads();
        const float* Ab = As + (t & 1)*128*20;
        const int kb = t << 4;
#pragma unroll
        for (int ks = 0; ks < 16; ks += 8) {
            unsigned af[4];
            int mm = wid*16 + qd;
            af[0] = fu(Ab[ mm     *20 + ks + tq    ]);
            af[1] = fu(Ab[(mm + 8)*20 + ks + tq    ]);
            af[2] = fu(Ab[ mm     *20 + ks + tq + 4]);
            af[3] = fu(Ab[(mm + 8)*20 + ks + tq + 4]);
#pragma unroll
            for (int nt = 0; nt < 32; nt++) {
                int nn = nt*8 + qd;
                unsigned bf[2];
                bf[0] = fu(Bs[nn*68 + kb + ks + tq    ]);
                bf[1] = fu(Bs[nn*68 + kb + ks + tq + 4]);
                mma_tf32(acc[nt], af, bf);
            }
        }
        __syncthreads();
    }
    float mx0 = -1e30f, mx1 = -1e30f;
#pragma unroll
    for (int nt = 0; nt < 32; nt++) {
        mx0 = fmaxf(mx0, fmaxf(acc[nt][0], acc[nt][1]));
        mx1 = fmaxf(mx1, fmaxf(acc[nt][2], acc[nt][3]));
    }
#pragma unroll
    for (int s = 1; s < 4; s <<= 1) {
        mx0 = fmaxf(mx0, __shfl_xor_sync(0xffffffffu, mx0, s));
        mx1 = fmaxf(mx1, __shfl_xor_sync(0xffffffffu, mx1, s));
    }
    float s0 = 0.f, s1 = 0.f;
#pragma unroll
    for (int nt = 0; nt < 32; nt++) {
        acc[nt][0] = __expf(acc[nt][0] - mx0);
        acc[nt][1] = __expf(acc[nt][1] - mx0);
        acc[nt][2] = __expf(acc[nt][2] - mx1);
        acc[nt][3] = __expf(acc[nt][3] - mx1);
        s0 += acc[nt][0] + acc[nt][1];
        s1 += acc[nt][2] + acc[nt][3];
    }
#pragma unroll
    for (int s = 1; s < 4; s <<= 1) {
        s0 += __shfl_xor_sync(0xffffffffu, s0, s);
        s1 += __shfl_xor_sync(0xffffffffu, s1, s);
    }
    const float i0 = 1.f / s0, i1 = 1.f / s1;
    const int r0 = m0 + wid*16 + qd;
    OutT* O0 = O + (size_t)bz*o_bs + (size_t)r0*256;
#pragma unroll
    for (int nt = 0; nt < 32; nt++) {
        int c = nt*8 + tq*2;
        if constexpr (sizeof(OutT) == 4) {
            *(float2*)((float*)O0 + c)         = make_float2(acc[nt][0]*i0, acc[nt][1]*i0);
            *(float2*)((float*)O0 + 8*256 + c) = make_float2(acc[nt][2]*i1, acc[nt][3]*i1);
        } else {
            *(__half2*)((__half*)O0 + c)         = __floats2half2_rn(acc[nt][0]*i0, acc[nt][1]*i0);
            *(__half2*)((__half*)O0 + 8*256 + c) = __floats2half2_rn(acc[nt][2]*i1, acc[nt][3]*i1);
        }
    }
}

// ------- sim3 with fused exp (fp16 store) + fp32 row-sum partials -----------
__global__ __launch_bounds__(128)
void sim3_exp_k(const float* __restrict__ QL, const float* __restrict__ Kg,
                __half* __restrict__ A3, float* __restrict__ RSP) {
    constexpr int LDA = 20;
    __shared__ float As[2*128*LDA];
    __shared__ float Bs[2*128*LDA];
    const int tid = threadIdx.x;
    const int wid = tid >> 5, lane = tid & 31;
    const int qd = lane >> 2, tq = lane & 3;
    const int wm = (wid >> 1) * 64, wn = (wid & 1) * 64;
    const int n0 = blockIdx.x * 128, m0 = blockIdx.y * 128;
    const int bz = blockIdx.z;
    const float* Ag = QL + (size_t)bz * ML * 64;
    const float* Bg = Kg + (size_t)bz * NTOK * 64;
    const uint32_t sA = s2u(As), sB = s2u(Bs);

    float acc[4][8][4] = {};
    auto load_tile = [&](int k0, int buf) {
        const uint32_t ab = sA + buf*128*LDA*4;
#pragma unroll
        for (int i = tid; i < 128*4; i += 128) {
            int r = i >> 2, kq = (i & 3) << 2;
            cp16(ab + (r*LDA + kq)*4, Ag + (size_t)(m0 + r)*64 + k0 + kq);
        }
        const uint32_t bb = s2u(Bs) + buf*128*LDA*4;
#pragma unroll
        for (int i = tid; i < 128*4; i += 128) {
            int n = i >> 2, kq = (i & 3) << 2;
            cp16(bb + (n*LDA + kq)*4, Bg + (size_t)(n0 + n)*64 + k0 + kq);
        }
        cp_commit();
    };

    load_tile(0, 0);
    for (int t = 0; t < 4; t++) {
        if (t + 1 < 4) { load_tile((t+1) << 4, (t+1) & 1); cp_wait1(); }
        else           { cp_wait0(); }
        __syncthreads();
        const float* Ab = As + (t & 1)*128*LDA;
        const float* Bb = Bs + (t & 1)*128*LDA;
#pragma unroll
        for (int ks = 0; ks < 16; ks += 8) {
            unsigned af[4][4];
#pragma unroll
            for (int mt = 0; mt < 4; mt++) {
                int mm = wm + mt*16 + qd;
                af[mt][0] = fu(Ab[ mm     *LDA + ks + tq    ]);
                af[mt][1] = fu(Ab[(mm + 8)*LDA + ks + tq    ]);
                af[mt][2] = fu(Ab[ mm     *LDA + ks + tq + 4]);
                af[mt][3] = fu(Ab[(mm + 8)*LDA + ks + tq + 4]);
            }
#pragma unroll
            for (int nt = 0; nt < 8; nt++) {
                int nn = wn + nt*8 + qd;
                unsigned bf[2];
                bf[0] = fu(Bb[nn*LDA + ks + tq    ]);
                bf[1] = fu(Bb[nn*LDA + ks + tq + 4]);
#pragma unroll
                for (int mt = 0; mt < 4; mt++)
                    mma_tf32(acc[mt][nt], af[mt], bf);
            }
        }
        __syncthreads();
    }

    __half* a3b = A3 + (size_t)bz * ML * NTOK;
    const int wh = wid & 1;
#pragma unroll
    for (int mt = 0; mt < 4; mt++) {
        const int r = wm + mt*16 + qd;
        float slo = 0.f, shi = 0.f;
#pragma unroll
        for (int nt = 0; nt < 8; nt++) {
            int c = n0 + wn + nt*8 + tq*2;
            float e0 = __expf(acc[mt][nt][0]);
            float e1 = __expf(acc[mt][nt][1]);
            float e2 = __expf(acc[mt][nt][2]);
            float e3 = __expf(acc[mt][nt][3]);
            *(__half2*)(a3b + (size_t)(m0 + r    )*NTOK + c) = __floats2half2_rn(e0, e1);
            *(__half2*)(a3b + (size_t)(m0 + r + 8)*NTOK + c) = __floats2half2_rn(e2, e3);
            slo += e0 + e1;
            shi += e2 + e3;
        }
#pragma unroll
        for (int s = 1; s < 4; s <<= 1) {
            slo += __shfl_xor_sync(0xffffffffu, slo, s);
            shi += __shfl_xor_sync(0xffffffffu, shi, s);
        }
        if (tq == 0) {
            RSP[(((size_t)bz*ML + (m0 + r    ))*64 + blockIdx.x)*2 + wh] = slo;
            RSP[(((size_t)bz*ML + (m0 + r + 8))*64 + blockIdx.x)*2 + wh] = shi;
        }
    }
}

__global__ __launch_bounds__(256)
void rowsum_k(const float* __restrict__ rsp, float* __restrict__ rs) {
    int row = blockIdx.x * 8 + (threadIdx.x >> 5);
    int lane = threadIdx.x & 31;
    const float* p = rsp + (size_t)row * 128;
    float s = p[lane] + p[lane + 32] + p[lane + 64] + p[lane + 96];
#pragma unroll
    for (int sh = 16; sh > 0; sh >>= 1) s += __shfl_xor_sync(0xffffffffu, s, sh);
    if (lane == 0) rs[row] = s;
}

// ---------------- small kernels ----------------
__global__ void init_scal_k(int* scal) { if (threadIdx.x < 2) scal[threadIdx.x] = 0; }

__global__ __launch_bounds__(256) void landmarks_k(
        const float* __restrict__ q, const float* __restrict__ k,
        float* __restrict__ ql, float* __restrict__ kl) {
    int idx = blockIdx.x * 256 + threadIdx.x;
    int dd = idx & 63, j = (idx >> 6) & 255, bh = idx >> 14;
    const float* qp = q + ((size_t)bh*NTOK + (size_t)j*LGRP)*64 + dd;
    const float* kp = k + ((size_t)bh*NTOK + (size_t)j*LGRP)*64 + dd;
    float sq = 0.f, sk = 0.f;
#pragma unroll
    for (int t = 0; t < LGRP; t++) { sq += qp[(size_t)t*64]; sk += kp[(size_t)t*64]; }
    ql[idx] = sq * (1.f/LGRP);
    kl[idx] = sk * (1.f/LGRP);
}

// v [bh][8192][64] fp32 -> vhT [bh][64][8192] fp16 (smem transpose)
__global__ __launch_bounds__(256) void vtrans_k(const float* __restrict__ v,
                                                __half* __restrict__ vhT) {
    __shared__ __half tile[64*136];
    const int bh = blockIdx.y, c0 = blockIdx.x * 128;
    const int tid = threadIdx.x;
    const float* vb = v + ((size_t)bh*NTOK + c0)*64;
#pragma unroll
    for (int i = tid; i < 128*64; i += 256) {
        int t = i >> 6, dd = i & 63;
        tile[dd*136 + t] = __float2half_rn(vb[(size_t)t*64 + dd]);
    }
    __syncthreads();
    __half* ob = vhT + (size_t)bh*64*NTOK + c0;
#pragma unroll
    for (int i = tid; i < 128*64; i += 256) {
        int dd = i >> 7, tt = i & 127;
#pragma unroll
        for (int rep = 0; rep < 1; rep++) { }
        ob[(size_t)dd*NTOK + tt] = tile[dd*136 + tt];
    }
    // handle remaining dd rows (256 threads cover 2 rows per iter; loop covers all)
}

__global__ __launch_bounds__(256) void scal_reduce_k(const float* __restrict__ a2, int* scal) {
    int idx = blockIdx.x, bh = blockIdx.y, mode = blockIdx.z, tid = threadIdx.x;
    const float* base = a2 + (size_t)bh * 65536;
    float v = (mode == 0) ? base[(size_t)idx*256 + tid] : base[(size_t)tid*256 + idx];
    __shared__ float red[256];
    red[tid] = v; __syncthreads();
    for (int s = 128; s > 0; s >>= 1) { if (tid < s) red[tid] += red[tid+s]; __syncthreads(); }
    if (tid == 0) atomicMax(&scal[mode], __float_as_int(red[0]));
}

__global__ __launch_bounds__(256) void zinit_k(const float* __restrict__ a2,
                                               const int* __restrict__ scal,
                                               float* __restrict__ z) {
    size_t idx = (size_t)blockIdx.x * 256 + threadIdx.x;
    float col = __int_as_float(scal[0]), row = __int_as_float(scal[1]);
    float rcp = 1.f / (col * row);
    int j = (int)(idx & 255), i = (int)((idx >> 8) & 255);
    size_t bh = idx >> 16;
    z[idx] = a2[(bh << 16) + (size_t)j*256 + i] * rcp;
}

__global__ __launch_bounds__(256) void t3_reduce_k(const float* __restrict__ part,
                                                   const float* __restrict__ rs,
                                                   float* __restrict__ t3) {
    int idx = blockIdx.x * 256 + threadIdx.x;
    float s = 0.f;
#pragma unroll
    for (int sp = 0; sp < 16; sp++) s += part[(size_t)sp*262144 + idx];
    t3[idx] = s / rs[idx >> 6];
}

// -------- tiled depthwise conv ----------
__global__ __launch_bounds__(256) void conv_add_k(const float* __restrict__ v,
                                                  const float* __restrict__ wc,
                                                  float* __restrict__ oh) {
    __shared__ float vt[160*64];
    const int chunk = blockIdx.x, bh = blockIdx.y;
    const int h = bh & 7;
    const int tid = threadIdx.x;
    const float* vb = v + (size_t)bh * NTOK * 64;
    const int base = chunk * 128 - 16;

    for (int idx = tid; idx < 160*64; idx += 256) {
        int row = idx >> 6, dd = idx & 63;
        int src = base + row;
        vt[idx] = (src >= 0 && src < NTOK) ? vb[(size_t)src*64 + dd] : 0.f;
    }
    float wreg[33];
#pragma unroll
    for (int t = 0; t < 33; t++) wreg[t] = wc[h*33 + t];
    __syncthreads();

    const int dd = tid & 63, quarter = tid >> 6;
    float vr[64];
#pragma unroll
    for (int x = 0; x < 64; x++) vr[x] = vt[(quarter*32 + x)*64 + dd];

    float* ohb = oh + ((size_t)bh*NTOK + (size_t)chunk*128 + quarter*32)*64 + dd;
#pragma unroll
    for (int j = 0; j < 32; j++) {
        float s = 0.f;
#pragma unroll
        for (int t = 0; t < 33; t++) s += wreg[t] * vr[j + t];
        ohb[(size_t)j*64] += s;
    }
}

// ---------------- orchestration ----------------
extern "C" void kernel_launch(void* const* d_in, const int* in_sizes, int n_in,
                              void* d_out, int out_size) {
    (void)in_sizes; (void)n_in; (void)out_size;
    const float* x      = (const float*)d_in[0];
    const float* w_qkv  = (const float*)d_in[1];
    const float* w_out  = (const float*)d_in[2];
    const float* b_out  = (const float*)d_in[3];
    const float* w_conv = (const float*)d_in[4];
    float* out = (float*)d_out;

    float *q,*k,*v,*ql,*kl,*rsp,*rs,*a2,*xz,*xz2,*w,*u,*z,*z2,*t3p,*t3,*oh;
    __half *a1h, *a3h, *vhT, *t2h;
    int* scal;
    cudaGetSymbolAddress((void**)&q,  g_q);
    cudaGetSymbolAddress((void**)&k,  g_k);
    cudaGetSymbolAddress((void**)&v,  g_v);
    cudaGetSymbolAddress((void**)&vhT,g_vhT);
    cudaGetSymbolAddress((void**)&ql, g_ql);
    cudaGetSymbolAddress((void**)&kl, g_kl);
    cudaGetSymbolAddress((void**)&a1h,g_attn1h);
    cudaGetSymbolAddress((void**)&a3h,g_attn3h);
    cudaGetSymbolAddress((void**)&rsp,g_rsp);
    cudaGetSymbolAddress((void**)&rs, g_rs);
    cudaGetSymbolAddress((void**)&a2, g_a2);
    cudaGetSymbolAddress((void**)&xz, g_xz);
    cudaGetSymbolAddress((void**)&xz2,g_xz2);
    cudaGetSymbolAddress((void**)&w,  g_w);
    cudaGetSymbolAddress((void**)&u,  g_u);
    cudaGetSymbolAddress((void**)&z,  g_z);
    cudaGetSymbolAddress((void**)&z2, g_z2);
    cudaGetSymbolAddress((void**)&t3p,g_t3p);
    cudaGetSymbolAddress((void**)&t3, g_t3);
    cudaGetSymbolAddress((void**)&t2h,g_t2h);
    cudaGetSymbolAddress((void**)&oh, g_oh);
    cudaGetSymbolAddress((void**)&scal, g_scal);

    static bool attr_done = false;
    if (!attr_done) {
        cudaFuncSetAttribute(gemm_rowsmax<float>,
            cudaFuncAttributeMaxDynamicSharedMemorySize, 90112);
        cudaFuncSetAttribute(gemm_rowsmax<__half>,
            cudaFuncAttributeMaxDynamicSharedMemorySize, 90112);
        attr_done = true;
    }

    init_scal_k<<<1, 32>>>(scal);

    // 1. QKV projection
    gemm_tc<128,128,64,64><<<dim3(12, 128, 1), 128>>>(
        AP{x, DIM, 0}, BP{w_qkv, 1536, 0}, EQKV{q, k, v}, DIM);

    // 1b. v -> fp16 transposed shadow for HMMA
    vtrans_k<<<dim3(64, BHN), 256>>>(v, vhT);

    // 2. landmark means
    landmarks_k<<<1024, 256>>>(q, k, ql, kl);

    // 3. attn2 = softmax(ql @ kl^T), fused (fp32 — feeds pinv)
    gemm_rowsmax<float><<<dim3(1, 2, BHN), 256, 90112>>>(
        ql, (size_t)ML*64, kl, (size_t)ML*64, a2, (size_t)ML*256);

    // 4. pinv init
    scal_reduce_k<<<dim3(256, BHN, 2), 256>>>(a2, scal);
    zinit_k<<<4096, 256>>>(a2, scal, z);

    // 5. Newton–Schulz x6, 3 GEMMs/iter
    float* xzc = xz;
    float* xzn = xz2;
    gemm_tc<64,64,32,32><<<dim3(4,4,BHN), 128>>>(
        AP{a2,256,65536}, BP{z,256,65536}, ES{xzc,256,65536,1.f}, 256);
    for (int it = 0; it < 6; it++) {
        float* zin  = (it & 1) ? z2 : z;
        float* zout = (it & 1) ? z  : z2;
        gemm_tc<64,64,32,32><<<dim3(4,4,BHN), 128>>>(
            AP{xzc,256,65536}, BP{xzc,256,65536}, EW{xzc, w}, 256);
        gemm_tc<64,64,32,32><<<dim3(4,4,BHN), 128>>>(
            AP{xzc,256,65536}, BP{w,256,65536}, EDiag{u,13.f}, 256);
        if (it < 5) {
            gemm_tc<64,64,32,32><<<dim3(4,4,2*BHN), 128>>>(
                APair{zin, xzc}, BPu{u}, EPair{zout, xzn}, 256);
            float* tmp = xzc; xzc = xzn; xzn = tmp;
        } else {
            gemm_tc<64,64,32,32><<<dim3(4,4,BHN), 128>>>(
                AP{zin,256,65536}, BP{u,256,65536}, ES{zout,256,65536,0.25f}, 256);
        }
    }
    // final z in g_z

    // 6. attn1 = softmax(q @ kl^T) -> fp16
    gemm_rowsmax<__half><<<dim3(1, 64, BHN), 256, 90112>>>(
        q, (size_t)NTOK*64, kl, (size_t)ML*64, a1h, (size_t)NTOK*256);

    // 7. a3 = exp(ql @ k^T) -> fp16, fp32 row-sum partials
    sim3_exp_k<<<dim3(64, 2, BHN), 128>>>(ql, k, a3h, rsp);
    rowsum_k<<<512, 256>>>(rsp, rs);

    // 8. t3 = (exp-scores @ v) / rowsum  (fp16 HMMA, transposed B, split-K x16)
    gemm_hh2<128,64,64,32><<<dim3(1, 2, BHN*16), 128>>>(
        AHSplit{a3h}, BTv{vhT}, EPart{t3p}, 512);
    t3_reduce_k<<<1024, 256>>>(t3p, rs, t3);

    // 9. t2 = z @ t3 -> fp16 transposed (feeds HMMA oh GEMM)
    gemm_tc<128,64,64,32><<<dim3(1, 2, BHN), 128>>>(
        AP{z, 256, 65536}, BP{t3, 64, (size_t)ML*64}, EST2{t2h}, 256);

    // 10. oh = attn1 @ t2  (fp16 HMMA, transposed B)
    gemm_hh2<128,64,64,32><<<dim3(1, 64, BHN), 128>>>(
        AH1{a1h}, BTt2{t2h}, ES{oh, 64, (size_t)NTOK*64, 1.f}, 256);

    // 11. residual depthwise conv (tiled)
    conv_add_k<<<dim3(64, BHN), 256>>>(v, w_conv, oh);

    // 12. out projection + residual
    gemm_tc<128,128,64,64><<<dim3(4, 128, 1), 128>>>(
        AGather{oh}, BP{w_out, DIM, 0}, EFin{x, b_out, out}, DIM);
}